// round 15
// baseline (speedup 1.0000x reference)
#include <cuda_runtime.h>
#include <cuda_bf16.h>
#include <math.h>
#include <stdint.h>

#define BB 256
#define HDN 1024
#define HWN 4096
#define NP 16

// ================= helpers =================
__device__ __forceinline__ uint32_t smem_to_u32(const void* p) {
    uint32_t a;
    asm("{ .reg .u64 tmp; cvta.to.shared.u64 tmp, %1; cvt.u32.u64 %0, tmp; }" : "=r"(a) : "l"(p));
    return a;
}
#define CP16(dst, src) \
    asm volatile("cp.async.cg.shared.global [%0], [%1], 16;" :: "r"((uint32_t)(dst)), "l"(src))
#define CP_COMMIT() asm volatile("cp.async.commit_group;" ::: "memory")
#define CP_WAIT(n)  asm volatile("cp.async.wait_group %0;" :: "n"(n) : "memory")

__device__ __forceinline__ void ldmx4(uint32_t* r, uint32_t a) {
    asm volatile("ldmatrix.sync.aligned.m8n8.x4.shared.b16 {%0,%1,%2,%3}, [%4];"
        : "=r"(r[0]), "=r"(r[1]), "=r"(r[2]), "=r"(r[3]) : "r"(a));
}
__device__ __forceinline__ void ldmx4t(uint32_t* r, uint32_t a) {
    asm volatile("ldmatrix.sync.aligned.m8n8.x4.trans.shared.b16 {%0,%1,%2,%3}, [%4];"
        : "=r"(r[0]), "=r"(r[1]), "=r"(r[2]), "=r"(r[3]) : "r"(a));
}
__device__ __forceinline__ void mma_bf16(float* c, const uint32_t* a, const uint32_t* b) {
    asm volatile(
        "mma.sync.aligned.m16n8k16.row.col.f32.bf16.bf16.f32 "
        "{%0,%1,%2,%3}, {%4,%5,%6,%7}, {%8,%9}, {%0,%1,%2,%3};"
        : "+f"(c[0]), "+f"(c[1]), "+f"(c[2]), "+f"(c[3])
        : "r"(a[0]), "r"(a[1]), "r"(a[2]), "r"(a[3]), "r"(b[0]), "r"(b[1]));
}

static __device__ __forceinline__ uint32_t sw128(uint32_t off) { return off ^ ((off >> 3) & 0x70); }

__device__ __forceinline__ uint32_t split_pack(float v0, float v1, uint32_t& lopack) {
    __nv_bfloat16 h0 = __float2bfloat16(v0);
    __nv_bfloat16 h1 = __float2bfloat16(v1);
    __nv_bfloat16 l0 = __float2bfloat16(v0 - __bfloat162float(h0));
    __nv_bfloat16 l1 = __float2bfloat16(v1 - __bfloat162float(h1));
    lopack = ((uint32_t)__bfloat16_as_ushort(l1) << 16) | (uint32_t)__bfloat16_as_ushort(l0);
    return ((uint32_t)__bfloat16_as_ushort(h1) << 16) | (uint32_t)__bfloat16_as_ushort(h0);
}

// ================= scratch (device globals) =================
__device__ float  g_part[NP * 256];
__device__ float  g_partial[8 * 256 * 1024];   // split-K partials (8 MB)

__device__ __align__(1024) __nv_bfloat16 g_A1h[2 * 64 * 8192];
__device__ __align__(1024) __nv_bfloat16 g_A1l[2 * 64 * 8192];
__device__ __align__(1024) __nv_bfloat16 g_A2h[2 * 16 * 8192];
__device__ __align__(1024) __nv_bfloat16 g_A2l[2 * 16 * 8192];
__device__ __align__(1024) __nv_bfloat16 g_A3h[2 * 16 * 8192];
__device__ __align__(1024) __nv_bfloat16 g_A3l[2 * 16 * 8192];
__device__ __align__(1024) __nv_bfloat16 g_WHh[2 * 16 * 4096];
__device__ __align__(1024) __nv_bfloat16 g_WHl[2 * 16 * 4096];

// ================= prep: convA (128 blocks) + convWH (32) + part (16) =================
__global__ __launch_bounds__(256) void prep_kernel(
    const float* __restrict__ A, const float* __restrict__ Wz,
    const float* __restrict__ Wum, const float* __restrict__ Wuv,
    const float* __restrict__ Wgm, const float* __restrict__ Wgv)
{
    int bx = blockIdx.x;
    int t = threadIdx.x;
    if (bx < 128) {
        int kc = bx >> 1, mt = bx & 1;
        int ml = t >> 1;
        int half = (t & 1) * 32;
        const float* src = A + (size_t)(mt * 128 + ml) * HWN + kc * 64 + half;
        size_t blk = ((size_t)mt * 64 + kc) * 8192;
        char* dh = (char*)(g_A1h + blk);
        char* dl = (char*)(g_A1l + blk);
#pragma unroll
        for (int i = 0; i < 32; i += 2) {
            float v0 = src[i], v1 = src[i + 1];
            uint32_t lo, hi = split_pack(v0, v1, lo);
            uint32_t off = sw128((uint32_t)(ml * 128 + (half + i) * 2));
            *(uint32_t*)(dh + off) = hi;
            *(uint32_t*)(dl + off) = lo;
        }
    } else if (bx < 160) {
        int q = bx - 128;
        int nt = q & 1, kc = q >> 1;
        int kl = t >> 2;
        int nq = (t & 3) * 16;
        int k = kc * 64 + kl;
        size_t blk = ((size_t)nt * 16 + kc) * 4096;
        char* dh = (char*)(g_WHh + blk);
        char* dl = (char*)(g_WHl + blk);
#pragma unroll 2
        for (int n2 = 0; n2 < 16; n2 += 2) {
            int nl = nq + n2;
            float vv[2];
#pragma unroll
            for (int e = 0; e < 2; e++) {
                int j = nt * 64 + nl + e;
                float v = 0.0f;
                if (j < 48)       v = Wum[k * 48 + j];
                else if (j < 96)  v = Wuv[k * 48 + (j - 48)];
                else if (j < 99)  v = Wgm[k * 3 + (j - 96)];
                else if (j < 102) v = Wgv[k * 3 + (j - 99)];
                vv[e] = v;
            }
            uint32_t lo, hi = split_pack(vv[0], vv[1], lo);
            uint32_t off = (uint32_t)kl * 128 + (((uint32_t)nl * 2) ^ (((uint32_t)kl & 7) << 4));
            *(uint32_t*)(dh + off) = hi;
            *(uint32_t*)(dl + off) = lo;
        }
    } else {
        int i = (bx - 160) * 256 + t;
        float s = 0.0f;
#pragma unroll
        for (int z = 0; z < 32; z++) s += Wz[z * 4096 + i];
        g_part[i] = 1.0f / (1.0f + expf(-s));
    }
}

// ====== 512-thread bf16-split GEMM, 128x128 tile, 3-stage pipeline, W via regs ======
// SMEM: 3 stages x 64KB: {Ah 16K | Al 16K | Bh 16K | Bl 16K}. W fp32 -> regs -> B smem.
template <int KBLK>
__global__ __launch_bounds__(512, 1) void mma_gemm512(
    const __nv_bfloat16* __restrict__ Ah, const __nv_bfloat16* __restrict__ Al,
    const float* __restrict__ Wraw,
    float* __restrict__ partial, int KCH)
{
    extern __shared__ char smem[];
    uint32_t sb = smem_to_u32(smem);
    int t = threadIdx.x, wid = t >> 5, l = t & 31;
    int nt = blockIdx.x, mt = blockIdx.y, ks = blockIdx.z;
    int kc0 = ks * KBLK;
    int ncol0 = nt * 128;

    const char* pAh = (const char*)Ah + ((size_t)mt * KCH + kc0) * 16384;
    const char* pAl = (const char*)Al + ((size_t)mt * KCH + kc0) * 16384;

    int m0 = (wid >> 2) * 32, n0 = (wid & 3) * 32;
    float acc[2][4][4];
#pragma unroll
    for (int a = 0; a < 2; a++)
#pragma unroll
        for (int b = 0; b < 4; b++)
#pragma unroll
            for (int c = 0; c < 4; c++) acc[a][b][c] = 0.0f;

    uint32_t xr = (uint32_t)(l & 7) << 4;
    uint32_t aRow   = (uint32_t)(m0 + (l & 7) + ((l >> 3) & 1) * 8) * 128;
    uint32_t kaddA2 = ((l >> 4) & 1) * 16;
    uint32_t bRowB = (uint32_t)((l & 7) + ((l >> 3) & 1) * 8) * 256;
    uint32_t nb0   = (uint32_t)(n0 + ((l >> 4) & 1) * 8) * 2;
    uint32_t xB1 = nb0 ^ xr;
    uint32_t xB2 = (nb0 + 32) ^ xr;

    int ckl = t >> 3;            // k-row 0..63
    int csg = (t & 7) * 16;      // 16 n-floats
    float4 wreg[4];

    auto loadW = [&](int chunk) {
        const float4* src = (const float4*)(Wraw +
            (size_t)((kc0 + chunk) * 64 + ckl) * 1024 + ncol0 + csg);
#pragma unroll
        for (int q = 0; q < 4; q++) wreg[q] = src[q];
    };

    auto issueA = [&](int chunk) {
        uint32_t st = sb + (uint32_t)(chunk % 3) * 65536;
        const char* sah = pAh + (size_t)chunk * 16384;
        const char* sal = pAl + (size_t)chunk * 16384;
#pragma unroll
        for (int i = 0; i < 2; i++) CP16(st + (t + i * 512) * 16, sah + (t + i * 512) * 16);
#pragma unroll
        for (int i = 0; i < 2; i++) CP16(st + 16384 + (t + i * 512) * 16, sal + (t + i * 512) * 16);
        CP_COMMIT();
    };

    loadW(0);
    issueA(0);
    if (KBLK > 1) issueA(1);

#pragma unroll 1
    for (int c = 0; c < KBLK; c++) {
        int sc = c % 3;
        __syncthreads();                    // MMA(c-1) done before reuse of its A stage
        if (c + 2 < KBLK) issueA(c + 2);

        {   // convert wreg (chunk c) -> B(stage sc)
            char* dhp = smem + sc * 65536 + 32768;
            char* dlp = dhp + 16384;
            uint32_t rowoff = (uint32_t)ckl * 256;
            uint32_t kx = ((uint32_t)ckl & 7) << 4;
#pragma unroll
            for (int q = 0; q < 4; q++) {
                float4 v = wreg[q];
                uint32_t lo0, hi0 = split_pack(v.x, v.y, lo0);
                uint32_t lo1, hi1 = split_pack(v.z, v.w, lo1);
                uint32_t off = rowoff + ((((uint32_t)(csg + q * 4)) * 2) ^ kx);
                *(uint2*)(dhp + off) = make_uint2(hi0, hi1);
                *(uint2*)(dlp + off) = make_uint2(lo0, lo1);
            }
        }
        if (c + 1 < KBLK) loadW(c + 1);     // LDG latency hidden behind MMA below

        if (c + 2 < KBLK)      { CP_WAIT(2); }
        else if (c + 1 < KBLK) { CP_WAIT(1); }
        else                   { CP_WAIT(0); }
        __syncthreads();

        uint32_t stA  = sb + (uint32_t)sc * 65536;
        uint32_t stBh = stA + 32768;
        uint32_t stBl = stA + 49152;
#pragma unroll
        for (int ks2 = 0; ks2 < 4; ks2++) {
            uint32_t xA = ((uint32_t)ks2 * 32 + kaddA2) ^ xr;
            uint32_t bbase = bRowB + (uint32_t)ks2 * 4096;
            uint32_t aH0[4], aH1[4], aL0[4], aL1[4], bH[8], bL[8];
            ldmx4(aH0, stA + aRow + xA);
            ldmx4(aH1, stA + aRow + 2048 + xA);
            ldmx4(aL0, stA + 16384 + aRow + xA);
            ldmx4(aL1, stA + 16384 + aRow + 2048 + xA);
            ldmx4t(bH,     stBh + bbase + xB1);
            ldmx4t(bH + 4, stBh + bbase + xB2);
            ldmx4t(bL,     stBl + bbase + xB1);
            ldmx4t(bL + 4, stBl + bbase + xB2);
#pragma unroll
            for (int mf = 0; mf < 2; mf++)
#pragma unroll
                for (int nf = 0; nf < 4; nf++)
                    mma_bf16(acc[mf][nf], mf ? aH1 : aH0, bH + nf * 2);
#pragma unroll
            for (int mf = 0; mf < 2; mf++)
#pragma unroll
                for (int nf = 0; nf < 4; nf++)
                    mma_bf16(acc[mf][nf], mf ? aH1 : aH0, bL + nf * 2);
#pragma unroll
            for (int mf = 0; mf < 2; mf++)
#pragma unroll
                for (int nf = 0; nf < 4; nf++)
                    mma_bf16(acc[mf][nf], mf ? aL1 : aL0, bH + nf * 2);
        }
    }

    int g = l >> 2, tg = l & 3;
#pragma unroll
    for (int mf = 0; mf < 2; mf++) {
#pragma unroll
        for (int nf = 0; nf < 4; nf++) {
            int gm = mt * 128 + m0 + mf * 16 + g;
            int gn = nt * 128 + n0 + nf * 8 + tg * 2;
            float* dst = partial + (size_t)ks * 262144 + (size_t)gm * 1024 + gn;
            *(float2*)dst = make_float2(acc[mf][nf][0], acc[mf][nf][1]);
            *(float2*)(dst + 8192) = make_float2(acc[mf][nf][2], acc[mf][nf][3]);
        }
    }
}

// ================= 256-thread GEMM (heads, pre-converted B) =================
template <int KBLK>
__global__ __launch_bounds__(256, 1) void mma_gemm_h(
    const __nv_bfloat16* __restrict__ Ah, const __nv_bfloat16* __restrict__ Al,
    const __nv_bfloat16* __restrict__ Bh, const __nv_bfloat16* __restrict__ Bl,
    float* __restrict__ partial, int KCH, int N)
{
    extern __shared__ char smem[];
    uint32_t sb = smem_to_u32(smem);
    int t = threadIdx.x, wid = t >> 5, l = t & 31;
    int nt = blockIdx.x, mt = blockIdx.y, ks = blockIdx.z;
    int kc0 = ks * KBLK;

    const char* pAh = (const char*)Ah + ((size_t)mt * KCH + kc0) * 16384;
    const char* pAl = (const char*)Al + ((size_t)mt * KCH + kc0) * 16384;
    const char* pBh = (const char*)Bh + ((size_t)nt * KCH + kc0) * 8192;
    const char* pBl = (const char*)Bl + ((size_t)nt * KCH + kc0) * 8192;

    int m0 = (wid >> 1) * 32, n0 = (wid & 1) * 32;
    float acc[2][4][4];
#pragma unroll
    for (int a = 0; a < 2; a++)
#pragma unroll
        for (int b = 0; b < 4; b++)
#pragma unroll
            for (int c = 0; c < 4; c++) acc[a][b][c] = 0.0f;

    uint32_t xr = (uint32_t)(l & 7) << 4;
    uint32_t aRow   = (uint32_t)(m0 + (l & 7) + ((l >> 3) & 1) * 8) * 128;
    uint32_t kaddA2 = ((l >> 4) & 1) * 16;
    uint32_t bRowB = (uint32_t)((l & 7) + ((l >> 3) & 1) * 8) * 128;
    uint32_t nb0   = (uint32_t)(n0 + ((l >> 4) & 1) * 8) * 2;
    uint32_t xB1 = nb0 ^ xr;
    uint32_t xB2 = (nb0 + 32) ^ xr;

    auto issue = [&](int chunk) {
        uint32_t sA = sb + (uint32_t)(chunk & 1) * 32768;
        const char* sah = pAh + (size_t)chunk * 16384;
        const char* sal = pAl + (size_t)chunk * 16384;
#pragma unroll
        for (int i = 0; i < 4; i++) CP16(sA + (t + i * 256) * 16, sah + (t + i * 256) * 16);
#pragma unroll
        for (int i = 0; i < 4; i++) CP16(sA + 16384 + (t + i * 256) * 16, sal + (t + i * 256) * 16);
        uint32_t sB = sb + 65536 + (uint32_t)(chunk & 1) * 16384;
        const char* sbh = pBh + (size_t)chunk * 8192;
        const char* sbl = pBl + (size_t)chunk * 8192;
#pragma unroll
        for (int i = 0; i < 2; i++) CP16(sB + (t + i * 256) * 16, sbh + (t + i * 256) * 16);
#pragma unroll
        for (int i = 0; i < 2; i++) CP16(sB + 8192 + (t + i * 256) * 16, sbl + (t + i * 256) * 16);
        CP_COMMIT();
    };

    issue(0);

#pragma unroll 1
    for (int c = 0; c < KBLK; c++) {
        if (c + 1 < KBLK) { issue(c + 1); CP_WAIT(1); }
        else              { CP_WAIT(0); }
        __syncthreads();

        uint32_t stA  = sb + (uint32_t)(c & 1) * 32768;
        uint32_t stBh = sb + 65536 + (uint32_t)(c & 1) * 16384;
        uint32_t stBl = stBh + 8192;
#pragma unroll
        for (int ks2 = 0; ks2 < 4; ks2++) {
            uint32_t xA = ((uint32_t)ks2 * 32 + kaddA2) ^ xr;
            uint32_t bbase = bRowB + (uint32_t)ks2 * 2048;
            uint32_t aH0[4], aH1[4], aL0[4], aL1[4], bH[8], bL[8];
            ldmx4(aH0, stA + aRow + xA);
            ldmx4(aH1, stA + aRow + 2048 + xA);
            ldmx4(aL0, stA + 16384 + aRow + xA);
            ldmx4(aL1, stA + 16384 + aRow + 2048 + xA);
            ldmx4t(bH,     stBh + bbase + xB1);
            ldmx4t(bH + 4, stBh + bbase + xB2);
            ldmx4t(bL,     stBl + bbase + xB1);
            ldmx4t(bL + 4, stBl + bbase + xB2);
#pragma unroll
            for (int mf = 0; mf < 2; mf++)
#pragma unroll
                for (int nf = 0; nf < 4; nf++)
                    mma_bf16(acc[mf][nf], mf ? aH1 : aH0, bH + nf * 2);
#pragma unroll
            for (int mf = 0; mf < 2; mf++)
#pragma unroll
                for (int nf = 0; nf < 4; nf++)
                    mma_bf16(acc[mf][nf], mf ? aH1 : aH0, bL + nf * 2);
#pragma unroll
            for (int mf = 0; mf < 2; mf++)
#pragma unroll
                for (int nf = 0; nf < 4; nf++)
                    mma_bf16(acc[mf][nf], mf ? aL1 : aL0, bH + nf * 2);
        }
        __syncthreads();
    }

    int g = l >> 2, tg = l & 3;
#pragma unroll
    for (int mf = 0; mf < 2; mf++) {
#pragma unroll
        for (int nf = 0; nf < 4; nf++) {
            int gm = mt * 128 + m0 + mf * 16 + g;
            int gn = nt * 64 + n0 + nf * 8 + tg * 2;
            float* dst = partial + (size_t)ks * 256 * N + (size_t)gm * N + gn;
            *(float2*)dst = make_float2(acc[mf][nf][0], acc[mf][nf][1]);
            *(float2*)(dst + (size_t)8 * N) = make_float2(acc[mf][nf][2], acc[mf][nf][3]);
        }
    }
}

// ============ epilogue: reduce split-K(NS) + bias + relu + pack (wide grid) ============
template <int NS>
__global__ __launch_bounds__(256) void epi_pack(
    const float* __restrict__ partial, const float* __restrict__ bias,
    __nv_bfloat16* __restrict__ outH, __nv_bfloat16* __restrict__ outL)
{
    int nt = blockIdx.x, mtile = blockIdx.y;
    int t = threadIdx.x;
    int rloc = t >> 4;
    int c4 = (t & 15) * 4;
    int row = mtile * 16 + rloc;
    int col0 = nt * 64 + c4;
    const float4* p = (const float4*)(partial + (size_t)row * 1024 + col0);
    float4 v = p[0];
#pragma unroll
    for (int k = 1; k < NS; k++) {
        float4 u = p[(size_t)k * 65536];
        v.x += u.x; v.y += u.y; v.z += u.z; v.w += u.w;
    }
    float4 bb = *(const float4*)&bias[col0];
    v.x = fmaxf(v.x + bb.x, 0.0f); v.y = fmaxf(v.y + bb.y, 0.0f);
    v.z = fmaxf(v.z + bb.z, 0.0f); v.w = fmaxf(v.w + bb.w, 0.0f);
    uint32_t lo0, hi0 = split_pack(v.x, v.y, lo0);
    uint32_t lo1, hi1 = split_pack(v.z, v.w, lo1);
    int mt = mtile >> 3;
    int ml = row & 127;
    size_t blk = ((size_t)mt * 16 + nt) * 8192;
    uint32_t off = sw128((uint32_t)(ml * 128 + c4 * 2));
    *(uint2*)((char*)(outH + blk) + off) = make_uint2(hi0, hi1);
    *(uint2*)((char*)(outL + blk) + off) = make_uint2(lo0, lo1);
}

// ========== fused: heads reduce+activations + composite + global transform ==========
__global__ __launch_bounds__(512) void composite_global(
    const float* __restrict__ partial, const float* __restrict__ M,
    const float* __restrict__ bum, const float* __restrict__ buv,
    const float* __restrict__ bgm, const float* __restrict__ bgv,
    const float* __restrict__ eps_u, const float* __restrict__ eps_g,
    float* __restrict__ out)
{
    extern __shared__ float sM[];          // 2 x 4096 floats (32KB dynamic)
    __shared__ float  sparts[NP][256];
    __shared__ float  sx[4096];
    __shared__ float4 spar[NP];
    __shared__ float4 sgp;
    __shared__ float  shr[128];
    __shared__ float  su[48];
    __shared__ float  sg[3];
    int b = blockIdx.x, t = threadIdx.x;
    uint32_t sMaddr = smem_to_u32(sM);
    const char* Mb = (const char*)(M + ((size_t)b << 16));

    {
        uint32_t dst = sMaddr + (uint32_t)t * 32;
        CP16(dst,      Mb + (size_t)t * 32);
        CP16(dst + 16, Mb + (size_t)t * 32 + 16);
        CP_COMMIT();
    }

    for (int i = t; i < NP * 256; i += 512) sparts[i >> 8][i & 255] = g_part[i];
    if (t < 128) {
        const float* p = partial + (size_t)b * 128 + t;
        shr[t] = p[0] + p[32768] + p[65536] + p[98304];
    }
    __syncthreads();

    if (t < 48) {
        float umu  = tanhf(shr[t] + bum[t]);
        float up   = shr[48 + t] + buv[t];
        float uvar = expf(up > -6.0f ? up : -6.0f);        // threshold(x,-6,-6)
        su[t] = umu + uvar * eps_u[b * 48 + t];
    } else if (t < 51) {
        int j = t - 48;
        float gmu  = tanhf(shr[96 + j] + bgm[j]);
        float gp   = shr[99 + j] + bgv[j];
        float gvar = expf(gp > -6.0f ? gp : 6.0f);         // threshold(x,-6,6) !
        sg[j] = gmu + gvar * eps_g[b * 3 + j];
    }
    __syncthreads();

    if (t < 16) {
        float a = su[3 * t], tx = su[3 * t + 1], ty = su[3 * t + 2];
        spar[t] = make_float4(cosf(a), sinf(a), tx, ty);
    } else if (t == 16) {
        sgp = make_float4(cosf(sg[0]), sinf(sg[0]), sg[1], sg[2]);
    }
    __syncthreads();

    int w  = t & 63;
    int hb = (t >> 6) * 8;
    float num[8], den[8];
#pragma unroll
    for (int i = 0; i < 8; i++) { num[i] = 0.0f; den[i] = 0.0f; }
    float xn = (2 * w + 1) * (1.0f / 64.0f) - 1.0f;

#pragma unroll 1
    for (int k = 0; k < 16; k++) {
        if (k + 1 < 16) {
            uint32_t dst = sMaddr + (uint32_t)((k + 1) & 1) * 16384 + (uint32_t)t * 32;
            const char* src = Mb + ((size_t)(k + 1) << 14) + (size_t)t * 32;
            CP16(dst,      src);
            CP16(dst + 16, src + 16);
            CP_COMMIT();
            CP_WAIT(1);
        } else {
            CP_WAIT(0);
        }
        __syncthreads();
        const float* Mk = sM + (k & 1) * 4096;

        float4 pp = spar[k];
        float c = pp.x, s = pp.y, tx = pp.z, ty = pp.w;
        int sx_ = (k & 3) * 8 - 12;
        int sy_ = (k >> 2) * 8 - 12;

        float fx = fminf(fmaxf(tx * 32.0f, -1e8f), 1e8f);
        float fy = fminf(fmaxf(ty * 32.0f, -1e8f), 1e8f);
        float ffx = floorf(fx), ffy = floorf(fy);
        float wx = fx - ffx, wy = fy - ffy;
        int dx0 = (int)ffx, dy0 = (int)ffy;
        int x0 = w + dx0, xA = x0 + sx_;
        bool vx0 = ((unsigned)x0 < 64u) && ((unsigned)xA < 64u);
        bool vx1 = ((unsigned)(x0 + 1) < 64u) && ((unsigned)(xA + 1) < 64u);

        float gxc = c * xn + tx;
        float gyc = s * xn + ty;
        int iox = 24 - sx_, ioy = 24 - sy_;
        float foxlo = (float)iox - 1.0f, foxhi = (float)iox + 16.0f;
        float foylo = (float)ioy - 1.0f, foyhi = (float)ioy + 16.0f;
        const float* pk = &sparts[k][0];

        auto rowv = [&](int y0) -> float {
            int yA = y0 + sy_;
            float a = 0.0f, bb = 0.0f;
            if (((unsigned)y0 < 64u) & ((unsigned)yA < 64u)) {
                const float* r = Mk + yA * 64 + xA;
                if (vx0) a = r[0];
                if (vx1) bb = r[1];
            }
            return a + wx * (bb - a);
        };
        float prev = rowv(hb + dy0);
#pragma unroll
        for (int i = 0; i < 8; i++) {
            int h = hb + i;
            float cur = rowv(h + dy0 + 1);
            float km = prev + wy * (cur - prev);
            prev = cur;
            den[i] += km;

            float yn  = (2 * h + 1) * (1.0f / 64.0f) - 1.0f;
            float gx  = gxc - s * yn;
            float gy  = gyc + c * yn;
            float ppx = gx * 32.0f + 31.5f;
            float ppy = gy * 32.0f + 31.5f;
            if (ppx > foxlo && ppx < foxhi && ppy > foylo && ppy < foyhi) {
                float fjx = floorf(ppx), fjy = floorf(ppy);
                float ux = ppx - fjx, uy = ppy - fjy;
                int px0 = (int)fjx - iox, py0 = (int)fjy - ioy;
                float p00 = 0.0f, p01 = 0.0f, p10 = 0.0f, p11 = 0.0f;
                if ((unsigned)py0 < 16u) {
                    if ((unsigned)px0 < 16u)       p00 = pk[py0 * 16 + px0];
                    if ((unsigned)(px0 + 1) < 16u) p01 = pk[py0 * 16 + px0 + 1];
                }
                if ((unsigned)(py0 + 1) < 16u) {
                    if ((unsigned)px0 < 16u)       p10 = pk[(py0 + 1) * 16 + px0];
                    if ((unsigned)(px0 + 1) < 16u) p11 = pk[(py0 + 1) * 16 + px0 + 1];
                }
                float q0 = p00 + ux * (p01 - p00);
                float q1 = p10 + ux * (p11 - p10);
                float xp = q0 + uy * (q1 - q0);
                num[i] += xp * km;
            }
        }
        __syncthreads();
    }

#pragma unroll
    for (int i = 0; i < 8; i++) {
        float d = den[i];
        d = (d == 0.0f) ? 1.0f : d;
        sx[(hb + i) * 64 + w] = num[i] / d;
    }
    __syncthreads();

    float4 gp = sgp;
#pragma unroll
    for (int i = 0; i < 8; i++) {
        int h = hb + i;
        float yn = (2 * h + 1) * (1.0f / 64.0f) - 1.0f;
        float gx = gp.x * xn - gp.y * yn + gp.z;
        float gy = gp.y * xn + gp.x * yn + gp.w;
        float px = fminf(fmaxf(gx * 32.0f + 31.5f, -8.0f), 72.0f);
        float py = fminf(fmaxf(gy * 32.0f + 31.5f, -8.0f), 72.0f);
        float fx0 = floorf(px), fy0 = floorf(py);
        float wx = px - fx0, wy = py - fy0;
        int x0 = (int)fx0, y0 = (int)fy0;
        float v00 = 0.0f, v01 = 0.0f, v10 = 0.0f, v11 = 0.0f;
        bool vx0 = (unsigned)x0 < 64u, vx1 = (unsigned)(x0 + 1) < 64u;
        bool vy0 = (unsigned)y0 < 64u, vy1 = (unsigned)(y0 + 1) < 64u;
        if (vx0 && vy0) v00 = sx[y0 * 64 + x0];
        if (vx1 && vy0) v01 = sx[y0 * 64 + x0 + 1];
        if (vx0 && vy1) v10 = sx[(y0 + 1) * 64 + x0];
        if (vx1 && vy1) v11 = sx[(y0 + 1) * 64 + x0 + 1];
        float r0 = v00 + wx * (v01 - v00);
        float r1 = v10 + wx * (v11 - v10);
        out[b * 4096 + h * 64 + w] = r0 + wy * (r1 - r0);
    }
}

// ================= launch =================
extern "C" void kernel_launch(void* const* d_in, const int* in_sizes, int n_in,
                              void* d_out, int out_size)
{
    const float* inputs = (const float*)d_in[0];
    const float* W1     = (const float*)d_in[1];
    const float* b1     = (const float*)d_in[2];
    const float* W2     = (const float*)d_in[3];
    const float* b2     = (const float*)d_in[4];
    const float* Wum    = (const float*)d_in[5];
    const float* bum    = (const float*)d_in[6];
    const float* Wuv    = (const float*)d_in[7];
    const float* buv    = (const float*)d_in[8];
    const float* Wgm    = (const float*)d_in[9];
    const float* bgm    = (const float*)d_in[10];
    const float* Wgv    = (const float*)d_in[11];
    const float* bgv    = (const float*)d_in[12];
    const float* Wz     = (const float*)d_in[13];
    const float* M      = (const float*)d_in[14];
    const float* eps_u  = (const float*)d_in[15];
    const float* eps_g  = (const float*)d_in[16];
    float* out = (float*)d_out;

    const int SMEM_512 = 196608;
    const int SMEM_H   = 98304;
    const int SMEM_CG  = 32768;
    cudaFuncSetAttribute(mma_gemm512<8>, cudaFuncAttributeMaxDynamicSharedMemorySize, SMEM_512);
    cudaFuncSetAttribute(mma_gemm512<2>, cudaFuncAttributeMaxDynamicSharedMemorySize, SMEM_512);
    cudaFuncSetAttribute(mma_gemm_h<4>,  cudaFuncAttributeMaxDynamicSharedMemorySize, SMEM_H);
    cudaFuncSetAttribute(composite_global, cudaFuncAttributeMaxDynamicSharedMemorySize, SMEM_CG);

    __nv_bfloat16 *A1h, *A1l, *A2h, *A2l, *A3h, *A3l, *WHh, *WHl;
    float* partial;
    cudaGetSymbolAddress((void**)&A1h, g_A1h); cudaGetSymbolAddress((void**)&A1l, g_A1l);
    cudaGetSymbolAddress((void**)&A2h, g_A2h); cudaGetSymbolAddress((void**)&A2l, g_A2l);
    cudaGetSymbolAddress((void**)&A3h, g_A3h); cudaGetSymbolAddress((void**)&A3l, g_A3l);
    cudaGetSymbolAddress((void**)&WHh, g_WHh); cudaGetSymbolAddress((void**)&WHl, g_WHl);
    cudaGetSymbolAddress((void**)&partial, g_partial);

    prep_kernel<<<176, 256>>>(inputs, Wz, Wum, Wuv, Wgm, Wgv);
    mma_gemm512<8><<<dim3(8, 2, 8), 512, SMEM_512>>>(A1h, A1l, W1, partial, 64);
    epi_pack<8><<<dim3(16, 16), 256>>>(partial, b1, A2h, A2l);
    mma_gemm512<2><<<dim3(8, 2, 8), 512, SMEM_512>>>(A2h, A2l, W2, partial, 16);
    epi_pack<8><<<dim3(16, 16), 256>>>(partial, b2, A3h, A3l);
    mma_gemm_h<4><<<dim3(2, 2, 4), 256, SMEM_H>>>(A3h, A3l, WHh, WHl, partial, 16, 128);
    composite_global<<<BB, 512, SMEM_CG>>>(partial, M, bum, buv, bgm, bgv, eps_u, eps_g, out);
}

// round 16
// speedup vs baseline: 1.0483x; 1.0483x over previous
#include <cuda_runtime.h>
#include <cuda_bf16.h>
#include <math.h>
#include <stdint.h>

#define BB 256
#define HDN 1024
#define HWN 4096
#define NP 16

// ================= helpers =================
__device__ __forceinline__ uint32_t smem_to_u32(const void* p) {
    uint32_t a;
    asm("{ .reg .u64 tmp; cvta.to.shared.u64 tmp, %1; cvt.u32.u64 %0, tmp; }" : "=r"(a) : "l"(p));
    return a;
}
#define CP16(dst, src) \
    asm volatile("cp.async.cg.shared.global [%0], [%1], 16;" :: "r"((uint32_t)(dst)), "l"(src))
#define CP_COMMIT() asm volatile("cp.async.commit_group;" ::: "memory")
#define CP_WAIT(n)  asm volatile("cp.async.wait_group %0;" :: "n"(n) : "memory")

__device__ __forceinline__ void ldmx4(uint32_t* r, uint32_t a) {
    asm volatile("ldmatrix.sync.aligned.m8n8.x4.shared.b16 {%0,%1,%2,%3}, [%4];"
        : "=r"(r[0]), "=r"(r[1]), "=r"(r[2]), "=r"(r[3]) : "r"(a));
}
__device__ __forceinline__ void ldmx4t(uint32_t* r, uint32_t a) {
    asm volatile("ldmatrix.sync.aligned.m8n8.x4.trans.shared.b16 {%0,%1,%2,%3}, [%4];"
        : "=r"(r[0]), "=r"(r[1]), "=r"(r[2]), "=r"(r[3]) : "r"(a));
}
__device__ __forceinline__ void mma_bf16(float* c, const uint32_t* a, const uint32_t* b) {
    asm volatile(
        "mma.sync.aligned.m16n8k16.row.col.f32.bf16.bf16.f32 "
        "{%0,%1,%2,%3}, {%4,%5,%6,%7}, {%8,%9}, {%0,%1,%2,%3};"
        : "+f"(c[0]), "+f"(c[1]), "+f"(c[2]), "+f"(c[3])
        : "r"(a[0]), "r"(a[1]), "r"(a[2]), "r"(a[3]), "r"(b[0]), "r"(b[1]));
}

static __device__ __forceinline__ uint32_t sw128(uint32_t off) { return off ^ ((off >> 3) & 0x70); }

__device__ __forceinline__ uint32_t split_pack(float v0, float v1, uint32_t& lopack) {
    __nv_bfloat16 h0 = __float2bfloat16(v0);
    __nv_bfloat16 h1 = __float2bfloat16(v1);
    __nv_bfloat16 l0 = __float2bfloat16(v0 - __bfloat162float(h0));
    __nv_bfloat16 l1 = __float2bfloat16(v1 - __bfloat162float(h1));
    lopack = ((uint32_t)__bfloat16_as_ushort(l1) << 16) | (uint32_t)__bfloat16_as_ushort(l0);
    return ((uint32_t)__bfloat16_as_ushort(h1) << 16) | (uint32_t)__bfloat16_as_ushort(h0);
}

// ================= scratch (device globals) =================
__device__ float  g_part[NP * 256];
__device__ float  g_partial[8 * 256 * 1024];   // split-K partials (8 MB)

__device__ __align__(1024) __nv_bfloat16 g_A1h[2 * 64 * 8192];
__device__ __align__(1024) __nv_bfloat16 g_A1l[2 * 64 * 8192];
__device__ __align__(1024) __nv_bfloat16 g_A2h[2 * 16 * 8192];
__device__ __align__(1024) __nv_bfloat16 g_A2l[2 * 16 * 8192];
__device__ __align__(1024) __nv_bfloat16 g_A3h[2 * 16 * 8192];
__device__ __align__(1024) __nv_bfloat16 g_A3l[2 * 16 * 8192];
__device__ __align__(1024) __nv_bfloat16 g_WHh[2 * 16 * 4096];
__device__ __align__(1024) __nv_bfloat16 g_WHl[2 * 16 * 4096];

// ================= prep: convA (128 blocks) + convWH (32) + part (16) =================
__global__ __launch_bounds__(256) void prep_kernel(
    const float* __restrict__ A, const float* __restrict__ Wz,
    const float* __restrict__ Wum, const float* __restrict__ Wuv,
    const float* __restrict__ Wgm, const float* __restrict__ Wgv)
{
    int bx = blockIdx.x;
    int t = threadIdx.x;
    if (bx < 128) {
        int kc = bx >> 1, mt = bx & 1;
        int ml = t >> 1;
        int half = (t & 1) * 32;
        const float* src = A + (size_t)(mt * 128 + ml) * HWN + kc * 64 + half;
        size_t blk = ((size_t)mt * 64 + kc) * 8192;
        char* dh = (char*)(g_A1h + blk);
        char* dl = (char*)(g_A1l + blk);
#pragma unroll
        for (int i = 0; i < 32; i += 2) {
            float v0 = src[i], v1 = src[i + 1];
            uint32_t lo, hi = split_pack(v0, v1, lo);
            uint32_t off = sw128((uint32_t)(ml * 128 + (half + i) * 2));
            *(uint32_t*)(dh + off) = hi;
            *(uint32_t*)(dl + off) = lo;
        }
    } else if (bx < 160) {
        int q = bx - 128;
        int nt = q & 1, kc = q >> 1;
        int kl = t >> 2;
        int nq = (t & 3) * 16;
        int k = kc * 64 + kl;
        size_t blk = ((size_t)nt * 16 + kc) * 4096;
        char* dh = (char*)(g_WHh + blk);
        char* dl = (char*)(g_WHl + blk);
#pragma unroll 2
        for (int n2 = 0; n2 < 16; n2 += 2) {
            int nl = nq + n2;
            float vv[2];
#pragma unroll
            for (int e = 0; e < 2; e++) {
                int j = nt * 64 + nl + e;
                float v = 0.0f;
                if (j < 48)       v = Wum[k * 48 + j];
                else if (j < 96)  v = Wuv[k * 48 + (j - 48)];
                else if (j < 99)  v = Wgm[k * 3 + (j - 96)];
                else if (j < 102) v = Wgv[k * 3 + (j - 99)];
                vv[e] = v;
            }
            uint32_t lo, hi = split_pack(vv[0], vv[1], lo);
            uint32_t off = (uint32_t)kl * 128 + (((uint32_t)nl * 2) ^ (((uint32_t)kl & 7) << 4));
            *(uint32_t*)(dh + off) = hi;
            *(uint32_t*)(dl + off) = lo;
        }
    } else {
        int i = (bx - 160) * 256 + t;
        float s = 0.0f;
#pragma unroll
        for (int z = 0; z < 32; z++) s += Wz[z * 4096 + i];
        g_part[i] = 1.0f / (1.0f + expf(-s));
    }
}

// ================= 512-thread bf16-split GEMM, 128x128 tile (R14 proven) =====
template <int KBLK>
__global__ __launch_bounds__(512, 1) void mma_gemm512(
    const __nv_bfloat16* __restrict__ Ah, const __nv_bfloat16* __restrict__ Al,
    const float* __restrict__ Wraw,
    float* __restrict__ partial, int KCH)
{
    extern __shared__ char smem[];
    uint32_t sb = smem_to_u32(smem);
    int t = threadIdx.x, wid = t >> 5, l = t & 31;
    int nt = blockIdx.x, mt = blockIdx.y, ks = blockIdx.z;
    int kc0 = ks * KBLK;
    int ncol0 = nt * 128;

    const char* pAh = (const char*)Ah + ((size_t)mt * KCH + kc0) * 16384;
    const char* pAl = (const char*)Al + ((size_t)mt * KCH + kc0) * 16384;

    int m0 = (wid >> 2) * 32, n0 = (wid & 3) * 32;
    float acc[2][4][4];
#pragma unroll
    for (int a = 0; a < 2; a++)
#pragma unroll
        for (int b = 0; b < 4; b++)
#pragma unroll
            for (int c = 0; c < 4; c++) acc[a][b][c] = 0.0f;

    uint32_t xr = (uint32_t)(l & 7) << 4;
    uint32_t aRow   = (uint32_t)(m0 + (l & 7) + ((l >> 3) & 1) * 8) * 128;
    uint32_t kaddA2 = ((l >> 4) & 1) * 16;
    uint32_t bRowB = (uint32_t)((l & 7) + ((l >> 3) & 1) * 8) * 256;
    uint32_t nb0   = (uint32_t)(n0 + ((l >> 4) & 1) * 8) * 2;
    uint32_t xB1 = nb0 ^ xr;
    uint32_t xB2 = (nb0 + 32) ^ xr;

    int ckl = t >> 3;
    int csg = (t & 7) * 16;

    auto issue = [&](int chunk) {
        uint32_t st = sb + (uint32_t)(chunk & 1) * 98304;
        const char* sah = pAh + (size_t)chunk * 16384;
        const char* sal = pAl + (size_t)chunk * 16384;
#pragma unroll
        for (int i = 0; i < 2; i++) CP16(st + (t + i * 512) * 16, sah + (t + i * 512) * 16);
#pragma unroll
        for (int i = 0; i < 2; i++) CP16(st + 16384 + (t + i * 512) * 16, sal + (t + i * 512) * 16);
        const char* swb = (const char*)Wraw +
            ((size_t)(kc0 + chunk) * 64 * 1024 + ncol0) * 4;
#pragma unroll
        for (int i = 0; i < 4; i++) {
            int c = t + i * 512;
            int row = c >> 5;
            int col = (c & 31) * 16;
            CP16(st + 65536 + row * 512 + col, swb + (size_t)row * 4096 + col);
        }
        CP_COMMIT();
    };

    issue(0);

#pragma unroll 1
    for (int c = 0; c < KBLK; c++) {
        if (c + 1 < KBLK) { issue(c + 1); CP_WAIT(1); }
        else              { CP_WAIT(0); }
        __syncthreads();

        {
            char* rawp = smem + (c & 1) * 98304 + 65536;
            char* dhp  = smem + (c & 1) * 98304 + 32768;
            char* dlp  = dhp + 16384;
            const float4* srcv = (const float4*)(rawp + ckl * 512 + csg * 4);
            uint32_t rowoff = (uint32_t)ckl * 256;
            uint32_t kx = ((uint32_t)ckl & 7) << 4;
#pragma unroll
            for (int q = 0; q < 4; q++) {
                float4 v = srcv[q];
                uint32_t lo0, hi0 = split_pack(v.x, v.y, lo0);
                uint32_t lo1, hi1 = split_pack(v.z, v.w, lo1);
                uint32_t off = rowoff + ((((uint32_t)(csg + q * 4)) * 2) ^ kx);
                *(uint2*)(dhp + off) = make_uint2(hi0, hi1);
                *(uint2*)(dlp + off) = make_uint2(lo0, lo1);
            }
            __syncthreads();
        }

        uint32_t stA  = sb + (uint32_t)(c & 1) * 98304;
        uint32_t stBh = stA + 32768;
        uint32_t stBl = stA + 49152;
#pragma unroll
        for (int ks2 = 0; ks2 < 4; ks2++) {
            uint32_t xA = ((uint32_t)ks2 * 32 + kaddA2) ^ xr;
            uint32_t bbase = bRowB + (uint32_t)ks2 * 4096;
            uint32_t aH0[4], aH1[4], aL0[4], aL1[4], bH[8], bL[8];
            ldmx4(aH0, stA + aRow + xA);
            ldmx4(aH1, stA + aRow + 2048 + xA);
            ldmx4(aL0, stA + 16384 + aRow + xA);
            ldmx4(aL1, stA + 16384 + aRow + 2048 + xA);
            ldmx4t(bH,     stBh + bbase + xB1);
            ldmx4t(bH + 4, stBh + bbase + xB2);
            ldmx4t(bL,     stBl + bbase + xB1);
            ldmx4t(bL + 4, stBl + bbase + xB2);
#pragma unroll
            for (int mf = 0; mf < 2; mf++)
#pragma unroll
                for (int nf = 0; nf < 4; nf++)
                    mma_bf16(acc[mf][nf], mf ? aH1 : aH0, bH + nf * 2);
#pragma unroll
            for (int mf = 0; mf < 2; mf++)
#pragma unroll
                for (int nf = 0; nf < 4; nf++)
                    mma_bf16(acc[mf][nf], mf ? aH1 : aH0, bL + nf * 2);
#pragma unroll
            for (int mf = 0; mf < 2; mf++)
#pragma unroll
                for (int nf = 0; nf < 4; nf++)
                    mma_bf16(acc[mf][nf], mf ? aL1 : aL0, bH + nf * 2);
        }
        __syncthreads();
    }

    int g = l >> 2, tg = l & 3;
#pragma unroll
    for (int mf = 0; mf < 2; mf++) {
#pragma unroll
        for (int nf = 0; nf < 4; nf++) {
            int gm = mt * 128 + m0 + mf * 16 + g;
            int gn = nt * 128 + n0 + nf * 8 + tg * 2;
            float* dst = partial + (size_t)ks * 262144 + (size_t)gm * 1024 + gn;
            *(float2*)dst = make_float2(acc[mf][nf][0], acc[mf][nf][1]);
            *(float2*)(dst + 8192) = make_float2(acc[mf][nf][2], acc[mf][nf][3]);
        }
    }
}

// ================= 256-thread GEMM (heads, pre-converted B) =================
template <int KBLK>
__global__ __launch_bounds__(256, 1) void mma_gemm_h(
    const __nv_bfloat16* __restrict__ Ah, const __nv_bfloat16* __restrict__ Al,
    const __nv_bfloat16* __restrict__ Bh, const __nv_bfloat16* __restrict__ Bl,
    float* __restrict__ partial, int KCH, int N)
{
    extern __shared__ char smem[];
    uint32_t sb = smem_to_u32(smem);
    int t = threadIdx.x, wid = t >> 5, l = t & 31;
    int nt = blockIdx.x, mt = blockIdx.y, ks = blockIdx.z;
    int kc0 = ks * KBLK;

    const char* pAh = (const char*)Ah + ((size_t)mt * KCH + kc0) * 16384;
    const char* pAl = (const char*)Al + ((size_t)mt * KCH + kc0) * 16384;
    const char* pBh = (const char*)Bh + ((size_t)nt * KCH + kc0) * 8192;
    const char* pBl = (const char*)Bl + ((size_t)nt * KCH + kc0) * 8192;

    int m0 = (wid >> 1) * 32, n0 = (wid & 1) * 32;
    float acc[2][4][4];
#pragma unroll
    for (int a = 0; a < 2; a++)
#pragma unroll
        for (int b = 0; b < 4; b++)
#pragma unroll
            for (int c = 0; c < 4; c++) acc[a][b][c] = 0.0f;

    uint32_t xr = (uint32_t)(l & 7) << 4;
    uint32_t aRow   = (uint32_t)(m0 + (l & 7) + ((l >> 3) & 1) * 8) * 128;
    uint32_t kaddA2 = ((l >> 4) & 1) * 16;
    uint32_t bRowB = (uint32_t)((l & 7) + ((l >> 3) & 1) * 8) * 128;
    uint32_t nb0   = (uint32_t)(n0 + ((l >> 4) & 1) * 8) * 2;
    uint32_t xB1 = nb0 ^ xr;
    uint32_t xB2 = (nb0 + 32) ^ xr;

    auto issue = [&](int chunk) {
        uint32_t sA = sb + (uint32_t)(chunk & 1) * 32768;
        const char* sah = pAh + (size_t)chunk * 16384;
        const char* sal = pAl + (size_t)chunk * 16384;
#pragma unroll
        for (int i = 0; i < 4; i++) CP16(sA + (t + i * 256) * 16, sah + (t + i * 256) * 16);
#pragma unroll
        for (int i = 0; i < 4; i++) CP16(sA + 16384 + (t + i * 256) * 16, sal + (t + i * 256) * 16);
        uint32_t sB = sb + 65536 + (uint32_t)(chunk & 1) * 16384;
        const char* sbh = pBh + (size_t)chunk * 8192;
        const char* sbl = pBl + (size_t)chunk * 8192;
#pragma unroll
        for (int i = 0; i < 2; i++) CP16(sB + (t + i * 256) * 16, sbh + (t + i * 256) * 16);
#pragma unroll
        for (int i = 0; i < 2; i++) CP16(sB + 8192 + (t + i * 256) * 16, sbl + (t + i * 256) * 16);
        CP_COMMIT();
    };

    issue(0);

#pragma unroll 1
    for (int c = 0; c < KBLK; c++) {
        if (c + 1 < KBLK) { issue(c + 1); CP_WAIT(1); }
        else              { CP_WAIT(0); }
        __syncthreads();

        uint32_t stA  = sb + (uint32_t)(c & 1) * 32768;
        uint32_t stBh = sb + 65536 + (uint32_t)(c & 1) * 16384;
        uint32_t stBl = stBh + 8192;
#pragma unroll
        for (int ks2 = 0; ks2 < 4; ks2++) {
            uint32_t xA = ((uint32_t)ks2 * 32 + kaddA2) ^ xr;
            uint32_t bbase = bRowB + (uint32_t)ks2 * 2048;
            uint32_t aH0[4], aH1[4], aL0[4], aL1[4], bH[8], bL[8];
            ldmx4(aH0, stA + aRow + xA);
            ldmx4(aH1, stA + aRow + 2048 + xA);
            ldmx4(aL0, stA + 16384 + aRow + xA);
            ldmx4(aL1, stA + 16384 + aRow + 2048 + xA);
            ldmx4t(bH,     stBh + bbase + xB1);
            ldmx4t(bH + 4, stBh + bbase + xB2);
            ldmx4t(bL,     stBl + bbase + xB1);
            ldmx4t(bL + 4, stBl + bbase + xB2);
#pragma unroll
            for (int mf = 0; mf < 2; mf++)
#pragma unroll
                for (int nf = 0; nf < 4; nf++)
                    mma_bf16(acc[mf][nf], mf ? aH1 : aH0, bH + nf * 2);
#pragma unroll
            for (int mf = 0; mf < 2; mf++)
#pragma unroll
                for (int nf = 0; nf < 4; nf++)
                    mma_bf16(acc[mf][nf], mf ? aH1 : aH0, bL + nf * 2);
#pragma unroll
            for (int mf = 0; mf < 2; mf++)
#pragma unroll
                for (int nf = 0; nf < 4; nf++)
                    mma_bf16(acc[mf][nf], mf ? aL1 : aL0, bH + nf * 2);
        }
        __syncthreads();
    }

    int g = l >> 2, tg = l & 3;
#pragma unroll
    for (int mf = 0; mf < 2; mf++) {
#pragma unroll
        for (int nf = 0; nf < 4; nf++) {
            int gm = mt * 128 + m0 + mf * 16 + g;
            int gn = nt * 64 + n0 + nf * 8 + tg * 2;
            float* dst = partial + (size_t)ks * 256 * N + (size_t)gm * N + gn;
            *(float2*)dst = make_float2(acc[mf][nf][0], acc[mf][nf][1]);
            *(float2*)(dst + (size_t)8 * N) = make_float2(acc[mf][nf][2], acc[mf][nf][3]);
        }
    }
}

// ============ epilogue: reduce split-K(NS) + bias + relu + pack (wide grid) ============
template <int NS>
__global__ __launch_bounds__(256) void epi_pack(
    const float* __restrict__ partial, const float* __restrict__ bias,
    __nv_bfloat16* __restrict__ outH, __nv_bfloat16* __restrict__ outL)
{
    int nt = blockIdx.x, mtile = blockIdx.y;
    int t = threadIdx.x;
    int rloc = t >> 4;
    int c4 = (t & 15) * 4;
    int row = mtile * 16 + rloc;
    int col0 = nt * 64 + c4;
    const float4* p = (const float4*)(partial + (size_t)row * 1024 + col0);
    float4 v = p[0];
#pragma unroll
    for (int k = 1; k < NS; k++) {
        float4 u = p[(size_t)k * 65536];
        v.x += u.x; v.y += u.y; v.z += u.z; v.w += u.w;
    }
    float4 bb = *(const float4*)&bias[col0];
    v.x = fmaxf(v.x + bb.x, 0.0f); v.y = fmaxf(v.y + bb.y, 0.0f);
    v.z = fmaxf(v.z + bb.z, 0.0f); v.w = fmaxf(v.w + bb.w, 0.0f);
    uint32_t lo0, hi0 = split_pack(v.x, v.y, lo0);
    uint32_t lo1, hi1 = split_pack(v.z, v.w, lo1);
    int mt = mtile >> 3;
    int ml = row & 127;
    size_t blk = ((size_t)mt * 16 + nt) * 8192;
    uint32_t off = sw128((uint32_t)(ml * 128 + c4 * 2));
    *(uint2*)((char*)(outH + blk) + off) = make_uint2(hi0, hi1);
    *(uint2*)((char*)(outL + blk) + off) = make_uint2(lo0, lo1);
}

// ========== fused: heads reduce+activations + composite (2-part ILP) + global ==========
// One block per batch b, 512 threads, 8 rows/thread.
// 4-plane smem ring (64KB dynamic); parts processed in pairs for 2x ILP.
__global__ __launch_bounds__(512, 2) void composite_global(
    const float* __restrict__ partial, const float* __restrict__ M,
    const float* __restrict__ bum, const float* __restrict__ buv,
    const float* __restrict__ bgm, const float* __restrict__ bgv,
    const float* __restrict__ eps_u, const float* __restrict__ eps_g,
    float* __restrict__ out)
{
    extern __shared__ float sM[];          // 4 x 4096 floats (64KB dynamic)
    __shared__ float  sparts[NP][256];
    __shared__ float  sx[4096];
    __shared__ float4 spar[NP];
    __shared__ float4 sgp;
    __shared__ float  shr[128];
    __shared__ float  su[48];
    __shared__ float  sg[3];
    int b = blockIdx.x, t = threadIdx.x;
    uint32_t sMaddr = smem_to_u32(sM);
    const char* Mb = (const char*)(M + ((size_t)b << 16));

    auto issuePair = [&](int p) {
        int pl0 = 2 * p, pl1 = 2 * p + 1;
        uint32_t d0 = sMaddr + (uint32_t)(pl0 & 3) * 16384 + (uint32_t)t * 32;
        const char* s0 = Mb + ((size_t)pl0 << 14) + (size_t)t * 32;
        CP16(d0, s0); CP16(d0 + 16, s0 + 16);
        uint32_t d1 = sMaddr + (uint32_t)(pl1 & 3) * 16384 + (uint32_t)t * 32;
        const char* s1 = Mb + ((size_t)pl1 << 14) + (size_t)t * 32;
        CP16(d1, s1); CP16(d1 + 16, s1 + 16);
        CP_COMMIT();
    };
    issuePair(0);
    issuePair(1);

    for (int i = t; i < NP * 256; i += 512) sparts[i >> 8][i & 255] = g_part[i];
    if (t < 128) {
        const float* p = partial + (size_t)b * 128 + t;
        shr[t] = p[0] + p[32768] + p[65536] + p[98304];
    }
    __syncthreads();

    if (t < 48) {
        float umu  = tanhf(shr[t] + bum[t]);
        float up   = shr[48 + t] + buv[t];
        float uvar = expf(up > -6.0f ? up : -6.0f);        // threshold(x,-6,-6)
        su[t] = umu + uvar * eps_u[b * 48 + t];
    } else if (t < 51) {
        int j = t - 48;
        float gmu  = tanhf(shr[96 + j] + bgm[j]);
        float gp   = shr[99 + j] + bgv[j];
        float gvar = expf(gp > -6.0f ? gp : 6.0f);         // threshold(x,-6,6) !
        sg[j] = gmu + gvar * eps_g[b * 3 + j];
    }
    __syncthreads();

    if (t < 16) {
        float a = su[3 * t], tx = su[3 * t + 1], ty = su[3 * t + 2];
        spar[t] = make_float4(cosf(a), sinf(a), tx, ty);
    } else if (t == 16) {
        sgp = make_float4(cosf(sg[0]), sinf(sg[0]), sg[1], sg[2]);
    }
    __syncthreads();

    int w  = t & 63;
    int hb = (t >> 6) * 8;
    float num[8], den[8];
#pragma unroll
    for (int i = 0; i < 8; i++) { num[i] = 0.0f; den[i] = 0.0f; }
    float xn = (2 * w + 1) * (1.0f / 64.0f) - 1.0f;

#pragma unroll 1
    for (int p = 0; p < 8; p++) {
        if (p < 7) { CP_WAIT(1); } else { CP_WAIT(0); }
        __syncthreads();
        int ka = 2 * p, kb = 2 * p + 1;
        const float* MA = sM + (ka & 3) * 4096;
        const float* MBp = sM + (kb & 3) * 4096;

        // ---- part A setup ----
        float4 pA = spar[ka];
        float cA = pA.x, sA = pA.y, txA = pA.z, tyA = pA.w;
        int sxA = (ka & 3) * 8 - 12, syA = (ka >> 2) * 8 - 12;
        float fxA = fminf(fmaxf(txA * 32.0f, -1e8f), 1e8f);
        float fyA = fminf(fmaxf(tyA * 32.0f, -1e8f), 1e8f);
        float ffxA = floorf(fxA), ffyA = floorf(fyA);
        float wxA = fxA - ffxA, wyA = fyA - ffyA;
        int dx0A = (int)ffxA, dy0A = (int)ffyA;
        int x0A = w + dx0A, xAA = x0A + sxA;
        bool vx0A = ((unsigned)x0A < 64u) && ((unsigned)xAA < 64u);
        bool vx1A = ((unsigned)(x0A + 1) < 64u) && ((unsigned)(xAA + 1) < 64u);
        float gxcA = cA * xn + txA, gycA = sA * xn + tyA;
        int ioxA = 24 - sxA, ioyA = 24 - syA;
        float fxloA = (float)ioxA - 1.0f, fxhiA = (float)ioxA + 16.0f;
        float fyloA = (float)ioyA - 1.0f, fyhiA = (float)ioyA + 16.0f;
        const float* pkA = &sparts[ka][0];

        // ---- part B setup ----
        float4 pB = spar[kb];
        float cB = pB.x, sB = pB.y, txB = pB.z, tyB = pB.w;
        int sxB = (kb & 3) * 8 - 12, syB = (kb >> 2) * 8 - 12;
        float fxB = fminf(fmaxf(txB * 32.0f, -1e8f), 1e8f);
        float fyB = fminf(fmaxf(tyB * 32.0f, -1e8f), 1e8f);
        float ffxB = floorf(fxB), ffyB = floorf(fyB);
        float wxB = fxB - ffxB, wyB = fyB - ffyB;
        int dx0B = (int)ffxB, dy0B = (int)ffyB;
        int x0B = w + dx0B, xAB = x0B + sxB;
        bool vx0B = ((unsigned)x0B < 64u) && ((unsigned)xAB < 64u);
        bool vx1B = ((unsigned)(x0B + 1) < 64u) && ((unsigned)(xAB + 1) < 64u);
        float gxcB = cB * xn + txB, gycB = sB * xn + tyB;
        int ioxB = 24 - sxB, ioyB = 24 - syB;
        float fxloB = (float)ioxB - 1.0f, fxhiB = (float)ioxB + 16.0f;
        float fyloB = (float)ioyB - 1.0f, fyhiB = (float)ioyB + 16.0f;
        const float* pkB = &sparts[kb][0];

        auto rowvA = [&](int y0) -> float {
            int yA = y0 + syA;
            float a = 0.0f, bb2 = 0.0f;
            if (((unsigned)y0 < 64u) & ((unsigned)yA < 64u)) {
                const float* r = MA + yA * 64 + xAA;
                if (vx0A) a = r[0];
                if (vx1A) bb2 = r[1];
            }
            return a + wxA * (bb2 - a);
        };
        auto rowvB = [&](int y0) -> float {
            int yA = y0 + syB;
            float a = 0.0f, bb2 = 0.0f;
            if (((unsigned)y0 < 64u) & ((unsigned)yA < 64u)) {
                const float* r = MBp + yA * 64 + xAB;
                if (vx0B) a = r[0];
                if (vx1B) bb2 = r[1];
            }
            return a + wxB * (bb2 - a);
        };
        float prevA = rowvA(hb + dy0A);
        float prevB = rowvB(hb + dy0B);
#pragma unroll
        for (int i = 0; i < 8; i++) {
            int h = hb + i;
            float curA = rowvA(h + dy0A + 1);
            float curB = rowvB(h + dy0B + 1);
            float kmA = prevA + wyA * (curA - prevA); prevA = curA;
            float kmB = prevB + wyB * (curB - prevB); prevB = curB;
            den[i] += kmA;
            den[i] += kmB;

            float yn = (2 * h + 1) * (1.0f / 64.0f) - 1.0f;
            // part A window
            {
                float gx = gxcA - sA * yn;
                float gy = gycA + cA * yn;
                float ppx = gx * 32.0f + 31.5f;
                float ppy = gy * 32.0f + 31.5f;
                if (ppx > fxloA && ppx < fxhiA && ppy > fyloA && ppy < fyhiA) {
                    float fjx = floorf(ppx), fjy = floorf(ppy);
                    float ux = ppx - fjx, uy = ppy - fjy;
                    int px0 = (int)fjx - ioxA, py0 = (int)fjy - ioyA;
                    float p00 = 0.0f, p01 = 0.0f, p10 = 0.0f, p11 = 0.0f;
                    if ((unsigned)py0 < 16u) {
                        if ((unsigned)px0 < 16u)       p00 = pkA[py0 * 16 + px0];
                        if ((unsigned)(px0 + 1) < 16u) p01 = pkA[py0 * 16 + px0 + 1];
                    }
                    if ((unsigned)(py0 + 1) < 16u) {
                        if ((unsigned)px0 < 16u)       p10 = pkA[(py0 + 1) * 16 + px0];
                        if ((unsigned)(px0 + 1) < 16u) p11 = pkA[(py0 + 1) * 16 + px0 + 1];
                    }
                    float q0 = p00 + ux * (p01 - p00);
                    float q1 = p10 + ux * (p11 - p10);
                    num[i] += (q0 + uy * (q1 - q0)) * kmA;
                }
            }
            // part B window
            {
                float gx = gxcB - sB * yn;
                float gy = gycB + cB * yn;
                float ppx = gx * 32.0f + 31.5f;
                float ppy = gy * 32.0f + 31.5f;
                if (ppx > fxloB && ppx < fxhiB && ppy > fyloB && ppy < fyhiB) {
                    float fjx = floorf(ppx), fjy = floorf(ppy);
                    float ux = ppx - fjx, uy = ppy - fjy;
                    int px0 = (int)fjx - ioxB, py0 = (int)fjy - ioyB;
                    float p00 = 0.0f, p01 = 0.0f, p10 = 0.0f, p11 = 0.0f;
                    if ((unsigned)py0 < 16u) {
                        if ((unsigned)px0 < 16u)       p00 = pkB[py0 * 16 + px0];
                        if ((unsigned)(px0 + 1) < 16u) p01 = pkB[py0 * 16 + px0 + 1];
                    }
                    if ((unsigned)(py0 + 1) < 16u) {
                        if ((unsigned)px0 < 16u)       p10 = pkB[(py0 + 1) * 16 + px0];
                        if ((unsigned)(px0 + 1) < 16u) p11 = pkB[(py0 + 1) * 16 + px0 + 1];
                    }
                    float q0 = p00 + ux * (p01 - p00);
                    float q1 = p10 + ux * (p11 - p10);
                    num[i] += (q0 + uy * (q1 - q0)) * kmB;
                }
            }
        }
        __syncthreads();
        if (p + 2 < 8) issuePair(p + 2);
    }

#pragma unroll
    for (int i = 0; i < 8; i++) {
        float d = den[i];
        d = (d == 0.0f) ? 1.0f : d;
        sx[(hb + i) * 64 + w] = num[i] / d;
    }
    __syncthreads();

    float4 gp = sgp;
#pragma unroll
    for (int i = 0; i < 8; i++) {
        int h = hb + i;
        float yn = (2 * h + 1) * (1.0f / 64.0f) - 1.0f;
        float gx = gp.x * xn - gp.y * yn + gp.z;
        float gy = gp.y * xn + gp.x * yn + gp.w;
        float px = fminf(fmaxf(gx * 32.0f + 31.5f, -8.0f), 72.0f);
        float py = fminf(fmaxf(gy * 32.0f + 31.5f, -8.0f), 72.0f);
        float fx0 = floorf(px), fy0 = floorf(py);
        float wx = px - fx0, wy = py - fy0;
        int x0 = (int)fx0, y0 = (int)fy0;
        float v00 = 0.0f, v01 = 0.0f, v10 = 0.0f, v11 = 0.0f;
        bool vx0 = (unsigned)x0 < 64u, vx1 = (unsigned)(x0 + 1) < 64u;
        bool vy0 = (unsigned)y0 < 64u, vy1 = (unsigned)(y0 + 1) < 64u;
        if (vx0 && vy0) v00 = sx[y0 * 64 + x0];
        if (vx1 && vy0) v01 = sx[y0 * 64 + x0 + 1];
        if (vx0 && vy1) v10 = sx[(y0 + 1) * 64 + x0];
        if (vx1 && vy1) v11 = sx[(y0 + 1) * 64 + x0 + 1];
        float r0 = v00 + wx * (v01 - v00);
        float r1 = v10 + wx * (v11 - v10);
        out[b * 4096 + h * 64 + w] = r0 + wy * (r1 - r0);
    }
}

// ================= launch =================
extern "C" void kernel_launch(void* const* d_in, const int* in_sizes, int n_in,
                              void* d_out, int out_size)
{
    const float* inputs = (const float*)d_in[0];
    const float* W1     = (const float*)d_in[1];
    const float* b1     = (const float*)d_in[2];
    const float* W2     = (const float*)d_in[3];
    const float* b2     = (const float*)d_in[4];
    const float* Wum    = (const float*)d_in[5];
    const float* bum    = (const float*)d_in[6];
    const float* Wuv    = (const float*)d_in[7];
    const float* buv    = (const float*)d_in[8];
    const float* Wgm    = (const float*)d_in[9];
    const float* bgm    = (const float*)d_in[10];
    const float* Wgv    = (const float*)d_in[11];
    const float* bgv    = (const float*)d_in[12];
    const float* Wz     = (const float*)d_in[13];
    const float* M      = (const float*)d_in[14];
    const float* eps_u  = (const float*)d_in[15];
    const float* eps_g  = (const float*)d_in[16];
    float* out = (float*)d_out;

    const int SMEM_512 = 196608;
    const int SMEM_H   = 98304;
    const int SMEM_CG  = 65536;
    cudaFuncSetAttribute(mma_gemm512<8>, cudaFuncAttributeMaxDynamicSharedMemorySize, SMEM_512);
    cudaFuncSetAttribute(mma_gemm512<2>, cudaFuncAttributeMaxDynamicSharedMemorySize, SMEM_512);
    cudaFuncSetAttribute(mma_gemm_h<4>,  cudaFuncAttributeMaxDynamicSharedMemorySize, SMEM_H);
    cudaFuncSetAttribute(composite_global, cudaFuncAttributeMaxDynamicSharedMemorySize, SMEM_CG);

    __nv_bfloat16 *A1h, *A1l, *A2h, *A2l, *A3h, *A3l, *WHh, *WHl;
    float* partial;
    cudaGetSymbolAddress((void**)&A1h, g_A1h); cudaGetSymbolAddress((void**)&A1l, g_A1l);
    cudaGetSymbolAddress((void**)&A2h, g_A2h); cudaGetSymbolAddress((void**)&A2l, g_A2l);
    cudaGetSymbolAddress((void**)&A3h, g_A3h); cudaGetSymbolAddress((void**)&A3l, g_A3l);
    cudaGetSymbolAddress((void**)&WHh, g_WHh); cudaGetSymbolAddress((void**)&WHl, g_WHl);
    cudaGetSymbolAddress((void**)&partial, g_partial);

    prep_kernel<<<176, 256>>>(inputs, Wz, Wum, Wuv, Wgm, Wgv);
    mma_gemm512<8><<<dim3(8, 2, 8), 512, SMEM_512>>>(A1h, A1l, W1, partial, 64);
    epi_pack<8><<<dim3(16, 16), 256>>>(partial, b1, A2h, A2l);
    mma_gemm512<2><<<dim3(8, 2, 8), 512, SMEM_512>>>(A2h, A2l, W2, partial, 16);
    epi_pack<8><<<dim3(16, 16), 256>>>(partial, b2, A3h, A3l);
    mma_gemm_h<4><<<dim3(2, 2, 4), 256, SMEM_H>>>(A3h, A3l, WHh, WHl, partial, 16, 128);
    composite_global<<<BB, 512, SMEM_CG>>>(partial, M, bum, buv, bgm, bgv, eps_u, eps_g, out);
}

// round 17
// speedup vs baseline: 1.1107x; 1.0596x over previous
#include <cuda_runtime.h>
#include <cuda_bf16.h>
#include <math.h>
#include <stdint.h>

#define BB 256
#define HDN 1024
#define HWN 4096
#define NP 16

// ================= helpers =================
__device__ __forceinline__ uint32_t smem_to_u32(const void* p) {
    uint32_t a;
    asm("{ .reg .u64 tmp; cvta.to.shared.u64 tmp, %1; cvt.u32.u64 %0, tmp; }" : "=r"(a) : "l"(p));
    return a;
}
#define CP16(dst, src) \
    asm volatile("cp.async.cg.shared.global [%0], [%1], 16;" :: "r"((uint32_t)(dst)), "l"(src))
#define CP_COMMIT() asm volatile("cp.async.commit_group;" ::: "memory")
#define CP_WAIT(n)  asm volatile("cp.async.wait_group %0;" :: "n"(n) : "memory")

__device__ __forceinline__ void ldmx4(uint32_t* r, uint32_t a) {
    asm volatile("ldmatrix.sync.aligned.m8n8.x4.shared.b16 {%0,%1,%2,%3}, [%4];"
        : "=r"(r[0]), "=r"(r[1]), "=r"(r[2]), "=r"(r[3]) : "r"(a));
}
__device__ __forceinline__ void ldmx4t(uint32_t* r, uint32_t a) {
    asm volatile("ldmatrix.sync.aligned.m8n8.x4.trans.shared.b16 {%0,%1,%2,%3}, [%4];"
        : "=r"(r[0]), "=r"(r[1]), "=r"(r[2]), "=r"(r[3]) : "r"(a));
}
__device__ __forceinline__ void mma_bf16(float* c, const uint32_t* a, const uint32_t* b) {
    asm volatile(
        "mma.sync.aligned.m16n8k16.row.col.f32.bf16.bf16.f32 "
        "{%0,%1,%2,%3}, {%4,%5,%6,%7}, {%8,%9}, {%0,%1,%2,%3};"
        : "+f"(c[0]), "+f"(c[1]), "+f"(c[2]), "+f"(c[3])
        : "r"(a[0]), "r"(a[1]), "r"(a[2]), "r"(a[3]), "r"(b[0]), "r"(b[1]));
}

static __device__ __forceinline__ uint32_t sw128(uint32_t off) { return off ^ ((off >> 3) & 0x70); }

__device__ __forceinline__ uint32_t split_pack(float v0, float v1, uint32_t& lopack) {
    __nv_bfloat16 h0 = __float2bfloat16(v0);
    __nv_bfloat16 h1 = __float2bfloat16(v1);
    __nv_bfloat16 l0 = __float2bfloat16(v0 - __bfloat162float(h0));
    __nv_bfloat16 l1 = __float2bfloat16(v1 - __bfloat162float(h1));
    lopack = ((uint32_t)__bfloat16_as_ushort(l1) << 16) | (uint32_t)__bfloat16_as_ushort(l0);
    return ((uint32_t)__bfloat16_as_ushort(h1) << 16) | (uint32_t)__bfloat16_as_ushort(h0);
}

// ================= scratch (device globals) =================
__device__ float  g_part[NP * 256];
__device__ float  g_partial[8 * 256 * 1024];   // split-K partials (8 MB)

__device__ __align__(1024) __nv_bfloat16 g_A1h[2 * 64 * 8192];
__device__ __align__(1024) __nv_bfloat16 g_A1l[2 * 64 * 8192];
__device__ __align__(1024) __nv_bfloat16 g_A2h[2 * 16 * 8192];
__device__ __align__(1024) __nv_bfloat16 g_A2l[2 * 16 * 8192];
__device__ __align__(1024) __nv_bfloat16 g_A3h[2 * 16 * 8192];
__device__ __align__(1024) __nv_bfloat16 g_A3l[2 * 16 * 8192];
__device__ __align__(1024) __nv_bfloat16 g_WHh[2 * 16 * 4096];
__device__ __align__(1024) __nv_bfloat16 g_WHl[2 * 16 * 4096];

// ================= prep: convA (128 blocks) + convWH (32) + part (16) =================
__global__ __launch_bounds__(256) void prep_kernel(
    const float* __restrict__ A, const float* __restrict__ Wz,
    const float* __restrict__ Wum, const float* __restrict__ Wuv,
    const float* __restrict__ Wgm, const float* __restrict__ Wgv)
{
    int bx = blockIdx.x;
    int t = threadIdx.x;
    if (bx < 128) {
        int kc = bx >> 1, mt = bx & 1;
        int ml = t >> 1;
        int half = (t & 1) * 32;
        const float* src = A + (size_t)(mt * 128 + ml) * HWN + kc * 64 + half;
        size_t blk = ((size_t)mt * 64 + kc) * 8192;
        char* dh = (char*)(g_A1h + blk);
        char* dl = (char*)(g_A1l + blk);
#pragma unroll
        for (int i = 0; i < 32; i += 2) {
            float v0 = src[i], v1 = src[i + 1];
            uint32_t lo, hi = split_pack(v0, v1, lo);
            uint32_t off = sw128((uint32_t)(ml * 128 + (half + i) * 2));
            *(uint32_t*)(dh + off) = hi;
            *(uint32_t*)(dl + off) = lo;
        }
    } else if (bx < 160) {
        int q = bx - 128;
        int nt = q & 1, kc = q >> 1;
        int kl = t >> 2;
        int nq = (t & 3) * 16;
        int k = kc * 64 + kl;
        size_t blk = ((size_t)nt * 16 + kc) * 4096;
        char* dh = (char*)(g_WHh + blk);
        char* dl = (char*)(g_WHl + blk);
#pragma unroll 2
        for (int n2 = 0; n2 < 16; n2 += 2) {
            int nl = nq + n2;
            float vv[2];
#pragma unroll
            for (int e = 0; e < 2; e++) {
                int j = nt * 64 + nl + e;
                float v = 0.0f;
                if (j < 48)       v = Wum[k * 48 + j];
                else if (j < 96)  v = Wuv[k * 48 + (j - 48)];
                else if (j < 99)  v = Wgm[k * 3 + (j - 96)];
                else if (j < 102) v = Wgv[k * 3 + (j - 99)];
                vv[e] = v;
            }
            uint32_t lo, hi = split_pack(vv[0], vv[1], lo);
            uint32_t off = (uint32_t)kl * 128 + (((uint32_t)nl * 2) ^ (((uint32_t)kl & 7) << 4));
            *(uint32_t*)(dh + off) = hi;
            *(uint32_t*)(dl + off) = lo;
        }
    } else {
        int i = (bx - 160) * 256 + t;
        float s = 0.0f;
#pragma unroll
        for (int z = 0; z < 32; z++) s += Wz[z * 4096 + i];
        g_part[i] = 1.0f / (1.0f + expf(-s));
    }
}

// ================= 512-thread bf16-split GEMM, 128x128 tile (R14 proven) =====
template <int KBLK>
__global__ __launch_bounds__(512, 1) void mma_gemm512(
    const __nv_bfloat16* __restrict__ Ah, const __nv_bfloat16* __restrict__ Al,
    const float* __restrict__ Wraw,
    float* __restrict__ partial, int KCH)
{
    extern __shared__ char smem[];
    uint32_t sb = smem_to_u32(smem);
    int t = threadIdx.x, wid = t >> 5, l = t & 31;
    int nt = blockIdx.x, mt = blockIdx.y, ks = blockIdx.z;
    int kc0 = ks * KBLK;
    int ncol0 = nt * 128;

    const char* pAh = (const char*)Ah + ((size_t)mt * KCH + kc0) * 16384;
    const char* pAl = (const char*)Al + ((size_t)mt * KCH + kc0) * 16384;

    int m0 = (wid >> 2) * 32, n0 = (wid & 3) * 32;
    float acc[2][4][4];
#pragma unroll
    for (int a = 0; a < 2; a++)
#pragma unroll
        for (int b = 0; b < 4; b++)
#pragma unroll
            for (int c = 0; c < 4; c++) acc[a][b][c] = 0.0f;

    uint32_t xr = (uint32_t)(l & 7) << 4;
    uint32_t aRow   = (uint32_t)(m0 + (l & 7) + ((l >> 3) & 1) * 8) * 128;
    uint32_t kaddA2 = ((l >> 4) & 1) * 16;
    uint32_t bRowB = (uint32_t)((l & 7) + ((l >> 3) & 1) * 8) * 256;
    uint32_t nb0   = (uint32_t)(n0 + ((l >> 4) & 1) * 8) * 2;
    uint32_t xB1 = nb0 ^ xr;
    uint32_t xB2 = (nb0 + 32) ^ xr;

    int ckl = t >> 3;
    int csg = (t & 7) * 16;

    auto issue = [&](int chunk) {
        uint32_t st = sb + (uint32_t)(chunk & 1) * 98304;
        const char* sah = pAh + (size_t)chunk * 16384;
        const char* sal = pAl + (size_t)chunk * 16384;
#pragma unroll
        for (int i = 0; i < 2; i++) CP16(st + (t + i * 512) * 16, sah + (t + i * 512) * 16);
#pragma unroll
        for (int i = 0; i < 2; i++) CP16(st + 16384 + (t + i * 512) * 16, sal + (t + i * 512) * 16);
        const char* swb = (const char*)Wraw +
            ((size_t)(kc0 + chunk) * 64 * 1024 + ncol0) * 4;
#pragma unroll
        for (int i = 0; i < 4; i++) {
            int c = t + i * 512;
            int row = c >> 5;
            int col = (c & 31) * 16;
            CP16(st + 65536 + row * 512 + col, swb + (size_t)row * 4096 + col);
        }
        CP_COMMIT();
    };

    issue(0);

#pragma unroll 1
    for (int c = 0; c < KBLK; c++) {
        if (c + 1 < KBLK) { issue(c + 1); CP_WAIT(1); }
        else              { CP_WAIT(0); }
        __syncthreads();

        {
            char* rawp = smem + (c & 1) * 98304 + 65536;
            char* dhp  = smem + (c & 1) * 98304 + 32768;
            char* dlp  = dhp + 16384;
            const float4* srcv = (const float4*)(rawp + ckl * 512 + csg * 4);
            uint32_t rowoff = (uint32_t)ckl * 256;
            uint32_t kx = ((uint32_t)ckl & 7) << 4;
#pragma unroll
            for (int q = 0; q < 4; q++) {
                float4 v = srcv[q];
                uint32_t lo0, hi0 = split_pack(v.x, v.y, lo0);
                uint32_t lo1, hi1 = split_pack(v.z, v.w, lo1);
                uint32_t off = rowoff + ((((uint32_t)(csg + q * 4)) * 2) ^ kx);
                *(uint2*)(dhp + off) = make_uint2(hi0, hi1);
                *(uint2*)(dlp + off) = make_uint2(lo0, lo1);
            }
            __syncthreads();
        }

        uint32_t stA  = sb + (uint32_t)(c & 1) * 98304;
        uint32_t stBh = stA + 32768;
        uint32_t stBl = stA + 49152;
#pragma unroll
        for (int ks2 = 0; ks2 < 4; ks2++) {
            uint32_t xA = ((uint32_t)ks2 * 32 + kaddA2) ^ xr;
            uint32_t bbase = bRowB + (uint32_t)ks2 * 4096;
            uint32_t aH0[4], aH1[4], aL0[4], aL1[4], bH[8], bL[8];
            ldmx4(aH0, stA + aRow + xA);
            ldmx4(aH1, stA + aRow + 2048 + xA);
            ldmx4(aL0, stA + 16384 + aRow + xA);
            ldmx4(aL1, stA + 16384 + aRow + 2048 + xA);
            ldmx4t(bH,     stBh + bbase + xB1);
            ldmx4t(bH + 4, stBh + bbase + xB2);
            ldmx4t(bL,     stBl + bbase + xB1);
            ldmx4t(bL + 4, stBl + bbase + xB2);
#pragma unroll
            for (int mf = 0; mf < 2; mf++)
#pragma unroll
                for (int nf = 0; nf < 4; nf++)
                    mma_bf16(acc[mf][nf], mf ? aH1 : aH0, bH + nf * 2);
#pragma unroll
            for (int mf = 0; mf < 2; mf++)
#pragma unroll
                for (int nf = 0; nf < 4; nf++)
                    mma_bf16(acc[mf][nf], mf ? aH1 : aH0, bL + nf * 2);
#pragma unroll
            for (int mf = 0; mf < 2; mf++)
#pragma unroll
                for (int nf = 0; nf < 4; nf++)
                    mma_bf16(acc[mf][nf], mf ? aL1 : aL0, bH + nf * 2);
        }
        __syncthreads();
    }

    int g = l >> 2, tg = l & 3;
#pragma unroll
    for (int mf = 0; mf < 2; mf++) {
#pragma unroll
        for (int nf = 0; nf < 4; nf++) {
            int gm = mt * 128 + m0 + mf * 16 + g;
            int gn = nt * 128 + n0 + nf * 8 + tg * 2;
            float* dst = partial + (size_t)ks * 262144 + (size_t)gm * 1024 + gn;
            *(float2*)dst = make_float2(acc[mf][nf][0], acc[mf][nf][1]);
            *(float2*)(dst + 8192) = make_float2(acc[mf][nf][2], acc[mf][nf][3]);
        }
    }
}

// ================= 256-thread GEMM (heads, pre-converted B) =================
template <int KBLK>
__global__ __launch_bounds__(256, 1) void mma_gemm_h(
    const __nv_bfloat16* __restrict__ Ah, const __nv_bfloat16* __restrict__ Al,
    const __nv_bfloat16* __restrict__ Bh, const __nv_bfloat16* __restrict__ Bl,
    float* __restrict__ partial, int KCH, int N)
{
    extern __shared__ char smem[];
    uint32_t sb = smem_to_u32(smem);
    int t = threadIdx.x, wid = t >> 5, l = t & 31;
    int nt = blockIdx.x, mt = blockIdx.y, ks = blockIdx.z;
    int kc0 = ks * KBLK;

    const char* pAh = (const char*)Ah + ((size_t)mt * KCH + kc0) * 16384;
    const char* pAl = (const char*)Al + ((size_t)mt * KCH + kc0) * 16384;
    const char* pBh = (const char*)Bh + ((size_t)nt * KCH + kc0) * 8192;
    const char* pBl = (const char*)Bl + ((size_t)nt * KCH + kc0) * 8192;

    int m0 = (wid >> 1) * 32, n0 = (wid & 1) * 32;
    float acc[2][4][4];
#pragma unroll
    for (int a = 0; a < 2; a++)
#pragma unroll
        for (int b = 0; b < 4; b++)
#pragma unroll
            for (int c = 0; c < 4; c++) acc[a][b][c] = 0.0f;

    uint32_t xr = (uint32_t)(l & 7) << 4;
    uint32_t aRow   = (uint32_t)(m0 + (l & 7) + ((l >> 3) & 1) * 8) * 128;
    uint32_t kaddA2 = ((l >> 4) & 1) * 16;
    uint32_t bRowB = (uint32_t)((l & 7) + ((l >> 3) & 1) * 8) * 128;
    uint32_t nb0   = (uint32_t)(n0 + ((l >> 4) & 1) * 8) * 2;
    uint32_t xB1 = nb0 ^ xr;
    uint32_t xB2 = (nb0 + 32) ^ xr;

    auto issue = [&](int chunk) {
        uint32_t sA = sb + (uint32_t)(chunk & 1) * 32768;
        const char* sah = pAh + (size_t)chunk * 16384;
        const char* sal = pAl + (size_t)chunk * 16384;
#pragma unroll
        for (int i = 0; i < 4; i++) CP16(sA + (t + i * 256) * 16, sah + (t + i * 256) * 16);
#pragma unroll
        for (int i = 0; i < 4; i++) CP16(sA + 16384 + (t + i * 256) * 16, sal + (t + i * 256) * 16);
        uint32_t sB = sb + 65536 + (uint32_t)(chunk & 1) * 16384;
        const char* sbh = pBh + (size_t)chunk * 8192;
        const char* sbl = pBl + (size_t)chunk * 8192;
#pragma unroll
        for (int i = 0; i < 2; i++) CP16(sB + (t + i * 256) * 16, sbh + (t + i * 256) * 16);
#pragma unroll
        for (int i = 0; i < 2; i++) CP16(sB + 8192 + (t + i * 256) * 16, sbl + (t + i * 256) * 16);
        CP_COMMIT();
    };

    issue(0);

#pragma unroll 1
    for (int c = 0; c < KBLK; c++) {
        if (c + 1 < KBLK) { issue(c + 1); CP_WAIT(1); }
        else              { CP_WAIT(0); }
        __syncthreads();

        uint32_t stA  = sb + (uint32_t)(c & 1) * 32768;
        uint32_t stBh = sb + 65536 + (uint32_t)(c & 1) * 16384;
        uint32_t stBl = stBh + 8192;
#pragma unroll
        for (int ks2 = 0; ks2 < 4; ks2++) {
            uint32_t xA = ((uint32_t)ks2 * 32 + kaddA2) ^ xr;
            uint32_t bbase = bRowB + (uint32_t)ks2 * 2048;
            uint32_t aH0[4], aH1[4], aL0[4], aL1[4], bH[8], bL[8];
            ldmx4(aH0, stA + aRow + xA);
            ldmx4(aH1, stA + aRow + 2048 + xA);
            ldmx4(aL0, stA + 16384 + aRow + xA);
            ldmx4(aL1, stA + 16384 + aRow + 2048 + xA);
            ldmx4t(bH,     stBh + bbase + xB1);
            ldmx4t(bH + 4, stBh + bbase + xB2);
            ldmx4t(bL,     stBl + bbase + xB1);
            ldmx4t(bL + 4, stBl + bbase + xB2);
#pragma unroll
            for (int mf = 0; mf < 2; mf++)
#pragma unroll
                for (int nf = 0; nf < 4; nf++)
                    mma_bf16(acc[mf][nf], mf ? aH1 : aH0, bH + nf * 2);
#pragma unroll
            for (int mf = 0; mf < 2; mf++)
#pragma unroll
                for (int nf = 0; nf < 4; nf++)
                    mma_bf16(acc[mf][nf], mf ? aH1 : aH0, bL + nf * 2);
#pragma unroll
            for (int mf = 0; mf < 2; mf++)
#pragma unroll
                for (int nf = 0; nf < 4; nf++)
                    mma_bf16(acc[mf][nf], mf ? aL1 : aL0, bH + nf * 2);
        }
        __syncthreads();
    }

    int g = l >> 2, tg = l & 3;
#pragma unroll
    for (int mf = 0; mf < 2; mf++) {
#pragma unroll
        for (int nf = 0; nf < 4; nf++) {
            int gm = mt * 128 + m0 + mf * 16 + g;
            int gn = nt * 64 + n0 + nf * 8 + tg * 2;
            float* dst = partial + (size_t)ks * 256 * N + (size_t)gm * N + gn;
            *(float2*)dst = make_float2(acc[mf][nf][0], acc[mf][nf][1]);
            *(float2*)(dst + (size_t)8 * N) = make_float2(acc[mf][nf][2], acc[mf][nf][3]);
        }
    }
}

// ============ epilogue: reduce split-K(NS) + bias + relu + pack (wide grid) ============
template <int NS>
__global__ __launch_bounds__(256) void epi_pack(
    const float* __restrict__ partial, const float* __restrict__ bias,
    __nv_bfloat16* __restrict__ outH, __nv_bfloat16* __restrict__ outL)
{
    int nt = blockIdx.x, mtile = blockIdx.y;
    int t = threadIdx.x;
    int rloc = t >> 4;
    int c4 = (t & 15) * 4;
    int row = mtile * 16 + rloc;
    int col0 = nt * 64 + c4;
    const float4* p = (const float4*)(partial + (size_t)row * 1024 + col0);
    float4 v = p[0];
#pragma unroll
    for (int k = 1; k < NS; k++) {
        float4 u = p[(size_t)k * 65536];
        v.x += u.x; v.y += u.y; v.z += u.z; v.w += u.w;
    }
    float4 bb = *(const float4*)&bias[col0];
    v.x = fmaxf(v.x + bb.x, 0.0f); v.y = fmaxf(v.y + bb.y, 0.0f);
    v.z = fmaxf(v.z + bb.z, 0.0f); v.w = fmaxf(v.w + bb.w, 0.0f);
    uint32_t lo0, hi0 = split_pack(v.x, v.y, lo0);
    uint32_t lo1, hi1 = split_pack(v.z, v.w, lo1);
    int mt = mtile >> 3;
    int ml = row & 127;
    size_t blk = ((size_t)mt * 16 + nt) * 8192;
    uint32_t off = sw128((uint32_t)(ml * 128 + c4 * 2));
    *(uint2*)((char*)(outH + blk) + off) = make_uint2(hi0, hi1);
    *(uint2*)((char*)(outL + blk) + off) = make_uint2(lo0, lo1);
}

// ========== fused: heads reduce+activations + composite (2-part ILP, global M) ==========
// One block per batch b, 512 threads, 8 rows/thread. No barriers in part loop.
__global__ __launch_bounds__(512) void composite_global(
    const float* __restrict__ partial, const float* __restrict__ M,
    const float* __restrict__ bum, const float* __restrict__ buv,
    const float* __restrict__ bgm, const float* __restrict__ bgv,
    const float* __restrict__ eps_u, const float* __restrict__ eps_g,
    float* __restrict__ out)
{
    __shared__ float  sparts[NP][256];
    __shared__ float  sx[4096];
    __shared__ float4 spar[NP];
    __shared__ float4 sgp;
    __shared__ float  shr[128];
    __shared__ float  su[48];
    __shared__ float  sg[3];
    int b = blockIdx.x, t = threadIdx.x;

    for (int i = t; i < NP * 256; i += 512) sparts[i >> 8][i & 255] = g_part[i];
    if (t < 128) {
        const float* p = partial + (size_t)b * 128 + t;
        shr[t] = p[0] + p[32768] + p[65536] + p[98304];
    }
    __syncthreads();

    if (t < 48) {
        float umu  = tanhf(shr[t] + bum[t]);
        float up   = shr[48 + t] + buv[t];
        float uvar = expf(up > -6.0f ? up : -6.0f);        // threshold(x,-6,-6)
        su[t] = umu + uvar * eps_u[b * 48 + t];
    } else if (t < 51) {
        int j = t - 48;
        float gmu  = tanhf(shr[96 + j] + bgm[j]);
        float gp   = shr[99 + j] + bgv[j];
        float gvar = expf(gp > -6.0f ? gp : 6.0f);         // threshold(x,-6,6) !
        sg[j] = gmu + gvar * eps_g[b * 3 + j];
    }
    __syncthreads();

    if (t < 16) {
        float a = su[3 * t], tx = su[3 * t + 1], ty = su[3 * t + 2];
        spar[t] = make_float4(cosf(a), sinf(a), tx, ty);
    } else if (t == 16) {
        sgp = make_float4(cosf(sg[0]), sinf(sg[0]), sg[1], sg[2]);
    }
    __syncthreads();

    int w  = t & 63;
    int hb = (t >> 6) * 8;
    float num[8], den[8];
#pragma unroll
    for (int i = 0; i < 8; i++) { num[i] = 0.0f; den[i] = 0.0f; }
    float xn = (2 * w + 1) * (1.0f / 64.0f) - 1.0f;

#pragma unroll 1
    for (int p = 0; p < 8; p++) {
        int ka = 2 * p, kb = 2 * p + 1;
        const float* MA  = M + ((size_t)((b << 4) + ka) << 12);
        const float* MBp = M + ((size_t)((b << 4) + kb) << 12);

        // ---- part A setup ----
        float4 pA = spar[ka];
        float cA = pA.x, sA = pA.y, txA = pA.z, tyA = pA.w;
        int sxA = (ka & 3) * 8 - 12, syA = (ka >> 2) * 8 - 12;
        float fxA = fminf(fmaxf(txA * 32.0f, -1e8f), 1e8f);
        float fyA = fminf(fmaxf(tyA * 32.0f, -1e8f), 1e8f);
        float ffxA = floorf(fxA), ffyA = floorf(fyA);
        float wxA = fxA - ffxA, wyA = fyA - ffyA;
        int dx0A = (int)ffxA, dy0A = (int)ffyA;
        int x0A = w + dx0A, xAA = x0A + sxA;
        bool vx0A = ((unsigned)x0A < 64u) && ((unsigned)xAA < 64u);
        bool vx1A = ((unsigned)(x0A + 1) < 64u) && ((unsigned)(xAA + 1) < 64u);
        float gxcA = cA * xn + txA, gycA = sA * xn + tyA;
        int ioxA = 24 - sxA, ioyA = 24 - syA;
        float fxloA = (float)ioxA - 1.0f, fxhiA = (float)ioxA + 16.0f;
        float fyloA = (float)ioyA - 1.0f, fyhiA = (float)ioyA + 16.0f;
        const float* pkA = &sparts[ka][0];

        // ---- part B setup ----
        float4 pB = spar[kb];
        float cB = pB.x, sB = pB.y, txB = pB.z, tyB = pB.w;
        int sxB = (kb & 3) * 8 - 12, syB = (kb >> 2) * 8 - 12;
        float fxB = fminf(fmaxf(txB * 32.0f, -1e8f), 1e8f);
        float fyB = fminf(fmaxf(tyB * 32.0f, -1e8f), 1e8f);
        float ffxB = floorf(fxB), ffyB = floorf(fyB);
        float wxB = fxB - ffxB, wyB = fyB - ffyB;
        int dx0B = (int)ffxB, dy0B = (int)ffyB;
        int x0B = w + dx0B, xAB = x0B + sxB;
        bool vx0B = ((unsigned)x0B < 64u) && ((unsigned)xAB < 64u);
        bool vx1B = ((unsigned)(x0B + 1) < 64u) && ((unsigned)(xAB + 1) < 64u);
        float gxcB = cB * xn + txB, gycB = sB * xn + tyB;
        int ioxB = 24 - sxB, ioyB = 24 - syB;
        float fxloB = (float)ioxB - 1.0f, fxhiB = (float)ioxB + 16.0f;
        float fyloB = (float)ioyB - 1.0f, fyhiB = (float)ioyB + 16.0f;
        const float* pkB = &sparts[kb][0];

        auto rowvA = [&](int y0) -> float {
            int yA = y0 + syA;
            float a = 0.0f, bb2 = 0.0f;
            if (((unsigned)y0 < 64u) & ((unsigned)yA < 64u)) {
                const float* r = MA + yA * 64 + xAA;
                if (vx0A) a = r[0];
                if (vx1A) bb2 = r[1];
            }
            return a + wxA * (bb2 - a);
        };
        auto rowvB = [&](int y0) -> float {
            int yA = y0 + syB;
            float a = 0.0f, bb2 = 0.0f;
            if (((unsigned)y0 < 64u) & ((unsigned)yA < 64u)) {
                const float* r = MBp + yA * 64 + xAB;
                if (vx0B) a = r[0];
                if (vx1B) bb2 = r[1];
            }
            return a + wxB * (bb2 - a);
        };
        float prevA = rowvA(hb + dy0A);
        float prevB = rowvB(hb + dy0B);
#pragma unroll
        for (int i = 0; i < 8; i++) {
            int h = hb + i;
            float curA = rowvA(h + dy0A + 1);
            float curB = rowvB(h + dy0B + 1);
            float kmA = prevA + wyA * (curA - prevA); prevA = curA;
            float kmB = prevB + wyB * (curB - prevB); prevB = curB;
            den[i] += kmA;
            den[i] += kmB;

            float yn = (2 * h + 1) * (1.0f / 64.0f) - 1.0f;
            // part A window
            {
                float gx = gxcA - sA * yn;
                float gy = gycA + cA * yn;
                float ppx = gx * 32.0f + 31.5f;
                float ppy = gy * 32.0f + 31.5f;
                if (ppx > fxloA && ppx < fxhiA && ppy > fyloA && ppy < fyhiA) {
                    float fjx = floorf(ppx), fjy = floorf(ppy);
                    float ux = ppx - fjx, uy = ppy - fjy;
                    int px0 = (int)fjx - ioxA, py0 = (int)fjy - ioyA;
                    float p00 = 0.0f, p01 = 0.0f, p10 = 0.0f, p11 = 0.0f;
                    if ((unsigned)py0 < 16u) {
                        if ((unsigned)px0 < 16u)       p00 = pkA[py0 * 16 + px0];
                        if ((unsigned)(px0 + 1) < 16u) p01 = pkA[py0 * 16 + px0 + 1];
                    }
                    if ((unsigned)(py0 + 1) < 16u) {
                        if ((unsigned)px0 < 16u)       p10 = pkA[(py0 + 1) * 16 + px0];
                        if ((unsigned)(px0 + 1) < 16u) p11 = pkA[(py0 + 1) * 16 + px0 + 1];
                    }
                    float q0 = p00 + ux * (p01 - p00);
                    float q1 = p10 + ux * (p11 - p10);
                    num[i] += (q0 + uy * (q1 - q0)) * kmA;
                }
            }
            // part B window
            {
                float gx = gxcB - sB * yn;
                float gy = gycB + cB * yn;
                float ppx = gx * 32.0f + 31.5f;
                float ppy = gy * 32.0f + 31.5f;
                if (ppx > fxloB && ppx < fxhiB && ppy > fyloB && ppy < fyhiB) {
                    float fjx = floorf(ppx), fjy = floorf(ppy);
                    float ux = ppx - fjx, uy = ppy - fjy;
                    int px0 = (int)fjx - ioxB, py0 = (int)fjy - ioyB;
                    float p00 = 0.0f, p01 = 0.0f, p10 = 0.0f, p11 = 0.0f;
                    if ((unsigned)py0 < 16u) {
                        if ((unsigned)px0 < 16u)       p00 = pkB[py0 * 16 + px0];
                        if ((unsigned)(px0 + 1) < 16u) p01 = pkB[py0 * 16 + px0 + 1];
                    }
                    if ((unsigned)(py0 + 1) < 16u) {
                        if ((unsigned)px0 < 16u)       p10 = pkB[(py0 + 1) * 16 + px0];
                        if ((unsigned)(px0 + 1) < 16u) p11 = pkB[(py0 + 1) * 16 + px0 + 1];
                    }
                    float q0 = p00 + ux * (p01 - p00);
                    float q1 = p10 + ux * (p11 - p10);
                    num[i] += (q0 + uy * (q1 - q0)) * kmB;
                }
            }
        }
    }

#pragma unroll
    for (int i = 0; i < 8; i++) {
        float d = den[i];
        d = (d == 0.0f) ? 1.0f : d;
        sx[(hb + i) * 64 + w] = num[i] / d;
    }
    __syncthreads();

    float4 gp = sgp;
#pragma unroll
    for (int i = 0; i < 8; i++) {
        int h = hb + i;
        float yn = (2 * h + 1) * (1.0f / 64.0f) - 1.0f;
        float gx = gp.x * xn - gp.y * yn + gp.z;
        float gy = gp.y * xn + gp.x * yn + gp.w;
        float px = fminf(fmaxf(gx * 32.0f + 31.5f, -8.0f), 72.0f);
        float py = fminf(fmaxf(gy * 32.0f + 31.5f, -8.0f), 72.0f);
        float fx0 = floorf(px), fy0 = floorf(py);
        float wx = px - fx0, wy = py - fy0;
        int x0 = (int)fx0, y0 = (int)fy0;
        float v00 = 0.0f, v01 = 0.0f, v10 = 0.0f, v11 = 0.0f;
        bool vx0 = (unsigned)x0 < 64u, vx1 = (unsigned)(x0 + 1) < 64u;
        bool vy0 = (unsigned)y0 < 64u, vy1 = (unsigned)(y0 + 1) < 64u;
        if (vx0 && vy0) v00 = sx[y0 * 64 + x0];
        if (vx1 && vy0) v01 = sx[y0 * 64 + x0 + 1];
        if (vx0 && vy1) v10 = sx[(y0 + 1) * 64 + x0];
        if (vx1 && vy1) v11 = sx[(y0 + 1) * 64 + x0 + 1];
        float r0 = v00 + wx * (v01 - v00);
        float r1 = v10 + wx * (v11 - v10);
        out[b * 4096 + h * 64 + w] = r0 + wy * (r1 - r0);
    }
}

// ================= launch =================
extern "C" void kernel_launch(void* const* d_in, const int* in_sizes, int n_in,
                              void* d_out, int out_size)
{
    const float* inputs = (const float*)d_in[0];
    const float* W1     = (const float*)d_in[1];
    const float* b1     = (const float*)d_in[2];
    const float* W2     = (const float*)d_in[3];
    const float* b2     = (const float*)d_in[4];
    const float* Wum    = (const float*)d_in[5];
    const float* bum    = (const float*)d_in[6];
    const float* Wuv    = (const float*)d_in[7];
    const float* buv    = (const float*)d_in[8];
    const float* Wgm    = (const float*)d_in[9];
    const float* bgm    = (const float*)d_in[10];
    const float* Wgv    = (const float*)d_in[11];
    const float* bgv    = (const float*)d_in[12];
    const float* Wz     = (const float*)d_in[13];
    const float* M      = (const float*)d_in[14];
    const float* eps_u  = (const float*)d_in[15];
    const float* eps_g  = (const float*)d_in[16];
    float* out = (float*)d_out;

    const int SMEM_512 = 196608;
    const int SMEM_H   = 98304;
    cudaFuncSetAttribute(mma_gemm512<8>, cudaFuncAttributeMaxDynamicSharedMemorySize, SMEM_512);
    cudaFuncSetAttribute(mma_gemm512<2>, cudaFuncAttributeMaxDynamicSharedMemorySize, SMEM_512);
    cudaFuncSetAttribute(mma_gemm_h<4>,  cudaFuncAttributeMaxDynamicSharedMemorySize, SMEM_H);

    __nv_bfloat16 *A1h, *A1l, *A2h, *A2l, *A3h, *A3l, *WHh, *WHl;
    float* partial;
    cudaGetSymbolAddress((void**)&A1h, g_A1h); cudaGetSymbolAddress((void**)&A1l, g_A1l);
    cudaGetSymbolAddress((void**)&A2h, g_A2h); cudaGetSymbolAddress((void**)&A2l, g_A2l);
    cudaGetSymbolAddress((void**)&A3h, g_A3h); cudaGetSymbolAddress((void**)&A3l, g_A3l);
    cudaGetSymbolAddress((void**)&WHh, g_WHh); cudaGetSymbolAddress((void**)&WHl, g_WHl);
    cudaGetSymbolAddress((void**)&partial, g_partial);

    prep_kernel<<<176, 256>>>(inputs, Wz, Wum, Wuv, Wgm, Wgv);
    mma_gemm512<8><<<dim3(8, 2, 8), 512, SMEM_512>>>(A1h, A1l, W1, partial, 64);
    epi_pack<8><<<dim3(16, 16), 256>>>(partial, b1, A2h, A2l);
    mma_gemm512<2><<<dim3(8, 2, 8), 512, SMEM_512>>>(A2h, A2l, W2, partial, 16);
    epi_pack<8><<<dim3(16, 16), 256>>>(partial, b2, A3h, A3l);
    mma_gemm_h<4><<<dim3(2, 2, 4), 256, SMEM_H>>>(A3h, A3l, WHh, WHl, partial, 16, 128);
    composite_global<<<BB, 512>>>(partial, M, bum, buv, bgm, bgv, eps_u, eps_g, out);
}